// round 12
// baseline (speedup 1.0000x reference)
#include <cuda_runtime.h>
#include <cuda_bf16.h>
#include <cstdint>

typedef unsigned long long ull;

#define SEQ   2048
#define BATCH 64
#define KIN   256
#define HID   256
#define G4H   1024   // 4*HID
#define MTOT  (SEQ * BATCH)   // 131072

// ---------------- scratch (device globals; no allocation allowed) ----------
__device__ float g_preact[(size_t)SEQ * BATCH * G4H];          // 512 MB
__device__ __nv_bfloat16 g_xh[(size_t)MTOT * KIN];             // 64 MB
__device__ __nv_bfloat16 g_xl[(size_t)MTOT * KIN];             // 64 MB
__device__ __nv_bfloat16 g_wih[(size_t)G4H * KIN];
__device__ __nv_bfloat16 g_wil[(size_t)G4H * KIN];
__device__ float g_bias[G4H];
__device__ float g_hbuf[2][BATCH * HID];        // legacy fallback path
__device__ unsigned int g_barG[256];            // legacy fallback path

// ---------------- small helpers -------------------------------------------
__device__ __forceinline__ uint32_t smem_u32(const void* p) {
    uint32_t a;
    asm("{ .reg .u64 t; cvta.to.shared.u64 t, %1; cvt.u32.u64 %0, t; }"
        : "=r"(a) : "l"(p));
    return a;
}
__device__ __forceinline__ ull ffma2(ull a, ull b, ull c) {
    ull d;
    asm("fma.rn.f32x2 %0, %1, %2, %3;" : "=l"(d) : "l"(a), "l"(b), "l"(c));
    return d;
}
__device__ __forceinline__ ull pk2(float x, float y) {
    ull r;
    asm("mov.b64 %0, {%1, %2};" : "=l"(r)
        : "r"(__float_as_uint(x)), "r"(__float_as_uint(y)));
    return r;
}
__device__ __forceinline__ void upk2(ull v, float& x, float& y) {
    uint32_t a, b;
    asm("mov.b64 {%0, %1}, %2;" : "=r"(a), "=r"(b) : "l"(v));
    x = __uint_as_float(a); y = __uint_as_float(b);
}
__device__ __forceinline__ float sigf(float x) {
    return __fdividef(1.f, 1.f + __expf(-x));
}
__device__ __forceinline__ float tanhf_(float x) { return 2.f * sigf(2.f * x) - 1.f; }

__device__ __forceinline__ void ldm_x4(uint32_t* r, uint32_t addr) {
    asm volatile("ldmatrix.sync.aligned.m8n8.x4.shared.b16 {%0,%1,%2,%3}, [%4];"
                 : "=r"(r[0]), "=r"(r[1]), "=r"(r[2]), "=r"(r[3]) : "r"(addr));
}
__device__ __forceinline__ void ldm_x2(uint32_t* r, uint32_t addr) {
    asm volatile("ldmatrix.sync.aligned.m8n8.x2.shared.b16 {%0,%1}, [%2];"
                 : "=r"(r[0]), "=r"(r[1]) : "r"(addr));
}
__device__ __forceinline__ void mma16816(float* d, const uint32_t* a,
                                         const uint32_t* b) {
    asm volatile(
        "mma.sync.aligned.m16n8k16.row.col.f32.bf16.bf16.f32 "
        "{%0,%1,%2,%3}, {%4,%5,%6,%7}, {%8,%9}, {%0,%1,%2,%3};"
        : "+f"(d[0]), "+f"(d[1]), "+f"(d[2]), "+f"(d[3])
        : "r"(a[0]), "r"(a[1]), "r"(a[2]), "r"(a[3]), "r"(b[0]), "r"(b[1]));
}

// ---- cluster / DSMEM / mbarrier primitives (all sm_90 baseline PTX) ------
__device__ __forceinline__ uint32_t mapa_u32(uint32_t addr, uint32_t rank) {
    uint32_t r;
    asm("mapa.shared::cluster.u32 %0, %1, %2;" : "=r"(r) : "r"(addr), "r"(rank));
    return r;
}
__device__ __forceinline__ void bulk_cp_cluster(uint32_t rdst, uint32_t lsrc,
                                                uint32_t bytes, uint32_t rmbar) {
    asm volatile(
        "cp.async.bulk.shared::cluster.shared::cta.mbarrier::complete_tx::bytes "
        "[%0], [%1], %2, [%3];"
        :: "r"(rdst), "r"(lsrc), "r"(bytes), "r"(rmbar) : "memory");
}
__device__ __forceinline__ void mbar_init_(uint32_t mbar, uint32_t cnt) {
    asm volatile("mbarrier.init.shared.b64 [%0], %1;" :: "r"(mbar), "r"(cnt)
                 : "memory");
}
__device__ __forceinline__ void mbar_expect(uint32_t mbar, uint32_t bytes) {
    asm volatile("mbarrier.arrive.expect_tx.shared.b64 _, [%0], %1;"
                 :: "r"(mbar), "r"(bytes) : "memory");
}
__device__ __forceinline__ void mbar_wait_cluster(uint32_t mbar, uint32_t parity) {
    asm volatile(
        "{\n\t.reg .pred P1;\n\t"
        "WL_%=:\n\t"
        "mbarrier.try_wait.parity.acquire.cluster.shared::cta.b64 P1, [%0], %1, 0x989680;\n\t"
        "@P1 bra.uni WD_%=;\n\t"
        "bra.uni WL_%=;\n\t"
        "WD_%=:\n\t}"
        :: "r"(mbar), "r"(parity) : "memory");
}

// ---------------------------------------------------------------------------
// Kernel 0a: convert x -> bf16 hi/lo planes
// ---------------------------------------------------------------------------
__global__ void __launch_bounds__(256) convert_x_kernel(const float* __restrict__ x)
{
    const size_t n4 = (size_t)MTOT * KIN / 4;
    for (size_t i = (size_t)blockIdx.x * blockDim.x + threadIdx.x; i < n4;
         i += (size_t)gridDim.x * blockDim.x) {
        float4 v = ((const float4*)x)[i];
        __nv_bfloat16 h0 = __float2bfloat16(v.x);
        __nv_bfloat16 h1 = __float2bfloat16(v.y);
        __nv_bfloat16 h2 = __float2bfloat16(v.z);
        __nv_bfloat16 h3 = __float2bfloat16(v.w);
        __nv_bfloat16 l0 = __float2bfloat16(v.x - __bfloat162float(h0));
        __nv_bfloat16 l1 = __float2bfloat16(v.y - __bfloat162float(h1));
        __nv_bfloat16 l2 = __float2bfloat16(v.z - __bfloat162float(h2));
        __nv_bfloat16 l3 = __float2bfloat16(v.w - __bfloat162float(h3));
        __nv_bfloat162 ph0 = {h0, h1}, ph1 = {h2, h3};
        __nv_bfloat162 pl0 = {l0, l1}, pl1 = {l2, l3};
        uint2 uh = {*(uint32_t*)&ph0, *(uint32_t*)&ph1};
        uint2 ul = {*(uint32_t*)&pl0, *(uint32_t*)&pl1};
        ((uint2*)g_xh)[i] = uh;
        ((uint2*)g_xl)[i] = ul;
    }
}

// ---------------------------------------------------------------------------
// Kernel 0b: convert Wi -> bf16 hi/lo, combine bias, reset barriers
// ---------------------------------------------------------------------------
__global__ void __launch_bounds__(256) convert_w_kernel(
    const float* __restrict__ Wi, const float* __restrict__ bi,
    const float* __restrict__ bh)
{
    const size_t tid = (size_t)blockIdx.x * blockDim.x + threadIdx.x;
    const size_t n4 = (size_t)G4H * KIN / 4;   // 65536
    if (tid < n4) {
        float4 v = ((const float4*)Wi)[tid];
        __nv_bfloat16 h0 = __float2bfloat16(v.x);
        __nv_bfloat16 h1 = __float2bfloat16(v.y);
        __nv_bfloat16 h2 = __float2bfloat16(v.z);
        __nv_bfloat16 h3 = __float2bfloat16(v.w);
        __nv_bfloat16 l0 = __float2bfloat16(v.x - __bfloat162float(h0));
        __nv_bfloat16 l1 = __float2bfloat16(v.y - __bfloat162float(h1));
        __nv_bfloat16 l2 = __float2bfloat16(v.z - __bfloat162float(h2));
        __nv_bfloat16 l3 = __float2bfloat16(v.w - __bfloat162float(h3));
        __nv_bfloat162 ph0 = {h0, h1}, ph1 = {h2, h3};
        __nv_bfloat162 pl0 = {l0, l1}, pl1 = {l2, l3};
        uint2 uh = {*(uint32_t*)&ph0, *(uint32_t*)&ph1};
        uint2 ul = {*(uint32_t*)&pl0, *(uint32_t*)&pl1};
        ((uint2*)g_wih)[tid] = uh;
        ((uint2*)g_wil)[tid] = ul;
    }
    if (tid < G4H) g_bias[tid] = bi[tid] + bh[tid];
    if (tid < 256) g_barG[tid] = 0u;
}

// ---------------------------------------------------------------------------
// Kernel 1: bf16x3 GEMM via mma.sync.m16n8k16  (unchanged, known-good)
// ---------------------------------------------------------------------------
#define LDP 40

__global__ void __launch_bounds__(256) gemm_mma_kernel()
{
    __shared__ __nv_bfloat16 Ah[128][LDP], Al[128][LDP];
    __shared__ __nv_bfloat16 Bh[128][LDP], Bl[128][LDP];

    const int tid = threadIdx.x;
    const int w = tid >> 5, l = tid & 31;
    const int m0 = blockIdx.y * 128, n0 = blockIdx.x * 128;
    const int wm = w & 1;
    const int wn = w >> 1;

    float acc[4][4][4];
#pragma unroll
    for (int mi = 0; mi < 4; mi++)
#pragma unroll
        for (int ni = 0; ni < 4; ni++)
#pragma unroll
            for (int q = 0; q < 4; q++) acc[mi][ni][q] = 0.f;

    for (int kc = 0; kc < KIN; kc += 32) {
#pragma unroll
        for (int tb = 0; tb < 4; tb++) {
            const __nv_bfloat16* src =
                (tb == 0) ? g_xh : (tb == 1) ? g_xl : (tb == 2) ? g_wih : g_wil;
            const int row0 = (tb < 2) ? m0 : n0;
            __nv_bfloat16 (*dst)[LDP] =
                (tb == 0) ? Ah : (tb == 1) ? Al : (tb == 2) ? Bh : Bl;
#pragma unroll
            for (int i = tid; i < 512; i += 256) {
                int r = i >> 2, q = i & 3;
                uint4 v = *(const uint4*)(src + (size_t)(row0 + r) * KIN + kc + q * 8);
                *(uint2*)&dst[r][q * 8]     = make_uint2(v.x, v.y);
                *(uint2*)&dst[r][q * 8 + 4] = make_uint2(v.z, v.w);
            }
        }
        __syncthreads();

#pragma unroll
        for (int p = 0; p < 3; p++) {
            const __nv_bfloat16 (*Ap)[LDP] = (p == 2) ? Al : Ah;
            const __nv_bfloat16 (*Bp)[LDP] = (p == 1) ? Bl : Bh;
#pragma unroll
            for (int ks = 0; ks < 2; ks++) {
                uint32_t af[4][4], bf[4][2];
#pragma unroll
                for (int mi = 0; mi < 4; mi++)
                    ldm_x4(af[mi], smem_u32(
                        &Ap[wm * 64 + mi * 16 + (l & 15)][ks * 16 + (l >> 4) * 8]));
#pragma unroll
                for (int ni = 0; ni < 4; ni++)
                    ldm_x2(bf[ni], smem_u32(
                        &Bp[wn * 32 + ni * 8 + (l & 7)][ks * 16 + ((l >> 3) & 1) * 8]));
#pragma unroll
                for (int mi = 0; mi < 4; mi++)
#pragma unroll
                    for (int ni = 0; ni < 4; ni++)
                        mma16816(acc[mi][ni], af[mi], bf[ni]);
            }
        }
        __syncthreads();
    }

#pragma unroll
    for (int ni = 0; ni < 4; ni++) {
        const int gn = n0 + wn * 32 + ni * 8 + (l & 3) * 2;
        const float b0 = g_bias[gn], b1 = g_bias[gn + 1];
#pragma unroll
        for (int mi = 0; mi < 4; mi++) {
            const int gm = m0 + wm * 64 + mi * 16 + (l >> 2);
            float2 v0 = {acc[mi][ni][0] + b0, acc[mi][ni][1] + b1};
            float2 v1 = {acc[mi][ni][2] + b0, acc[mi][ni][3] + b1};
            *(float2*)&g_preact[(size_t)gm * G4H + gn]       = v0;
            *(float2*)&g_preact[(size_t)(gm + 8) * G4H + gn] = v1;
        }
    }
}

// ---------------------------------------------------------------------------
// Kernel 2 (NEW): cluster recurrent kernel with BULK h-exchange.
// 128 blocks; cluster (16,1,1) = 16 j-slices of one batch-slice.
// Per step: gates stage 512B locally; 16 lanes each issue ONE 512B
// cp.async.bulk to one peer's incoming tile (DMA, off the LSU path).
// Incoming tile layout hs[parity][slice(16)][batch(8)][j(16)] is directly
// GEMM-readable; expect_tx posted one step early (race-free chain).
// ---------------------------------------------------------------------------
__global__ void __launch_bounds__(256, 1) lstm_rec_cluster(
    const float* __restrict__ h0, const float* __restrict__ c0,
    const float* __restrict__ Wh, float* __restrict__ out)
{
    __shared__ __align__(16) float hs[2][16][8][16];  // peer-written, 16KB
    __shared__ __align__(16) float stage[2][8][16];   // outgoing staging, 1KB
    __shared__ float reds[64 * 33];
    __shared__ ull   mbar[2];

    const int u   = threadIdx.x;
    const int jb  = blockIdx.x & 15;    // == cluster rank
    const int bb  = blockIdx.x >> 4;
    const int j0  = jb * 16;
    const int b0  = bb * 8;

    const int wid = u >> 5;
    const int l   = u & 31;
    const int ch  = wid >> 2;
    const int kq  = wid & 3;
    const int cmb = ch * 32 + l;
    const int g   = cmb >> 4;
    const int jj  = cmb & 15;

    const uint32_t mb0 = smem_u32(&mbar[0]);
    const uint32_t mb1 = smem_u32(&mbar[1]);

    if (u == 0) {
        mbar_init_(mb0, 1);
        mbar_init_(mb1, 1);
        asm volatile("fence.mbarrier_init.release.cluster;" ::: "memory");
        mbar_expect(mb1, 8192);   // serves copies issued during step 0
    }
    __syncthreads();
    asm volatile("barrier.cluster.arrive.aligned;" ::: "memory");

    // weights: 64 per thread, packed as f32x2 pairs
    ull wp[32];
    {
        const float* wrow = Wh + (size_t)(g * HID + j0 + jj) * HID + kq * 64;
#pragma unroll
        for (int q = 0; q < 16; q++) {
            float4 v = *(const float4*)&wrow[q * 4];
            wp[q * 2 + 0] = pk2(v.x, v.y);
            wp[q * 2 + 1] = pk2(v.z, v.w);
        }
    }

    const int tb = u >> 4;
    const int tj = u & 15;
    float cst = 0.f, hlast = 0.f;
    if (u < 128) cst = c0[(b0 + tb) * HID + j0 + tj];

    // load h0 into hs[0] in [slice][b][j16] layout
#pragma unroll
    for (int q = 0; q < 2; q++) {
        int f  = u * 2 + q;          // 0..511
        int b  = f >> 6;             // 0..7
        int ko = (f & 63) * 4;       // 0..252, mult of 4
        float4 v = *(const float4*)&h0[(size_t)(b0 + b) * HID + ko];
        *(float4*)&hs[0][ko >> 4][b][ko & 15] = v;
    }

    // preact for t=0
    float px0 = 0.f, px1 = 0.f, px2 = 0.f, px3 = 0.f;
    if (u < 128) {
        const float* pp = g_preact + ((size_t)(b0 + tb)) * G4H + j0 + tj;
        px0 = pp[0 * HID]; px1 = pp[1 * HID]; px2 = pp[2 * HID]; px3 = pp[3 * HID];
    }

    asm volatile("barrier.cluster.wait.aligned;" ::: "memory");
    __syncthreads();

    int ph[2] = {0, 0};

    for (int t = 0; t < SEQ; t++) {
        const int cur = t & 1, nxt = (t + 1) & 1;

        // expect for copies issued during step t+1 (they target B[cur])
        if (u == 0 && t + 3 <= SEQ) mbar_expect(cur ? mb1 : mb0, 8192);

        // prefetch preact t+1
        float nx0 = 0.f, nx1 = 0.f, nx2 = 0.f, nx3 = 0.f;
        if (u < 128) {
            int tn = (t + 1 < SEQ) ? (t + 1) : t;
            const float* pp = g_preact + ((size_t)tn * BATCH + b0 + tb) * G4H + j0 + tj;
            nx0 = pp[0 * HID]; nx1 = pp[1 * HID]; nx2 = pp[2 * HID]; nx3 = pp[3 * HID];
        }

        // packed-f32x2 GEMM over this thread's k-quarter
        // h[b][k] lives at hs[cur][k>>4][b][k&15]
        ull acc2[8];
#pragma unroll
        for (int b = 0; b < 8; b++) acc2[b] = 0ull;
        const float* hslab = &hs[cur][kq * 4][0][0];   // 4 slices x 128 floats
#pragma unroll
        for (int k4 = 0; k4 < 16; k4++) {
            const ull w0 = wp[k4 * 2 + 0], w1 = wp[k4 * 2 + 1];
            const int soff = (k4 >> 2) * 128 + (k4 & 3) * 4;
#pragma unroll
            for (int b = 0; b < 8; b++) {
                ulonglong2 hv = *(const ulonglong2*)&hslab[soff + b * 16];
                acc2[b] = ffma2(hv.x, w0, acc2[b]);
                acc2[b] = ffma2(hv.y, w1, acc2[b]);
            }
        }
#pragma unroll
        for (int b = 0; b < 8; b++) {
            float lo, hi; upk2(acc2[b], lo, hi);
            reds[cmb * 33 + kq * 8 + b] = lo + hi;
        }
        __syncthreads();

        if (u < 128) {
            float p[4];
#pragma unroll
            for (int gg = 0; gg < 4; gg++) {
                int cc = gg * 16 + tj;
                p[gg] = reds[cc * 33 + 0 + tb] + reds[cc * 33 + 8 + tb]
                      + reds[cc * 33 + 16 + tb] + reds[cc * 33 + 24 + tb];
            }
            p[0] += px0; p[1] += px1; p[2] += px2; p[3] += px3;

            float it = sigf(p[0]);
            float ft = sigf(p[1]);
            float ot = sigf(p[2]);
            float gt = tanhf_(p[3]);
            cst = cst * ft + it * gt;
            float ht = ot * tanhf_(cst);
            hlast = ht;

            out[((size_t)t * BATCH + b0 + tb) * HID + j0 + tj] = ht;
            stage[nxt][tb][tj] = ht;     // local staging for bulk broadcast
        }
        __syncthreads();

        if (t < SEQ - 1) {
            // 16 lanes: one 512B bulk copy each to peer rank u
            if (u < 16) {
                asm volatile("fence.proxy.async.shared::cta;" ::: "memory");
                const uint32_t lsrc = smem_u32(&stage[nxt][0][0]);
                const uint32_t ldst = smem_u32(&hs[nxt][jb][0][0]);
                const uint32_t lmb  = nxt ? mb1 : mb0;
                bulk_cp_cluster(mapa_u32(ldst, u), lsrc, 512, mapa_u32(lmb, u));
            }
            mbar_wait_cluster(nxt ? mb1 : mb0, ph[nxt]);
            ph[nxt] ^= 1;
        }
        px0 = nx0; px1 = nx1; px2 = nx2; px3 = nx3;
    }

    if (u < 128) {
        const size_t base = (size_t)SEQ * BATCH * HID;
        const int idx = (b0 + tb) * HID + j0 + tj;
        out[base + idx]               = hlast;
        out[base + BATCH * HID + idx] = cst;
    }

    asm volatile("barrier.cluster.arrive.aligned;" ::: "memory");
    asm volatile("barrier.cluster.wait.aligned;" ::: "memory");
}

// ---------------------------------------------------------------------------
// Kernel 2 (FALLBACK): round-10 L2-barrier version (known-good, 6568us total)
// ---------------------------------------------------------------------------
__global__ void __launch_bounds__(256, 1) lstm_rec_kernel(
    const float* __restrict__ h0, const float* __restrict__ c0,
    const float* __restrict__ Wh, float* __restrict__ out)
{
    __shared__ float hsf[8][256];
    __shared__ float reds[64 * 33];

    const int u   = threadIdx.x;
    const int jb  = blockIdx.x & 15;
    const int bb  = blockIdx.x >> 4;
    const int j0  = jb * 16;
    const int b0  = bb * 8;

    const int wid = u >> 5;
    const int l   = u & 31;
    const int ch  = wid >> 2;
    const int kq  = wid & 3;
    const int cmb = ch * 32 + l;
    const int g   = cmb >> 4;
    const int jj  = cmb & 15;

    ull wp[32];
    {
        const float* wrow = Wh + (size_t)(g * HID + j0 + jj) * HID + kq * 64;
#pragma unroll
        for (int q = 0; q < 16; q++) {
            float4 v = *(const float4*)&wrow[q * 4];
            wp[q * 2 + 0] = pk2(v.x, v.y);
            wp[q * 2 + 1] = pk2(v.z, v.w);
        }
    }

    const int tb = u >> 4;
    const int tj = u & 15;
    float cst = 0.f, hlast = 0.f;
    if (u < 128) cst = c0[(b0 + tb) * HID + j0 + tj];

    unsigned int* const cnt = &g_barG[bb * 32];

    float px0 = 0.f, px1 = 0.f, px2 = 0.f, px3 = 0.f;
    if (u < 128) {
        const float* pp = g_preact + ((size_t)(b0 + tb)) * G4H + j0 + tj;
        px0 = pp[0 * HID]; px1 = pp[1 * HID]; px2 = pp[2 * HID]; px3 = pp[3 * HID];
    }

    for (int t = 0; t < SEQ; t++) {
        {
            const float* hsrc = (t == 0) ? h0 : g_hbuf[t & 1];
#pragma unroll
            for (int q = 0; q < 2; q++) {
                int f  = u * 2 + q;
                int b  = f >> 6;
                int ko = (f & 63) * 4;
                float4 v = __ldcg((const float4*)&hsrc[(size_t)(b0 + b) * HID + ko]);
                *(float4*)&hsf[b][ko] = v;
            }
        }
        __syncthreads();

        float nx0 = 0.f, nx1 = 0.f, nx2 = 0.f, nx3 = 0.f;
        if (u < 128) {
            int tn = (t + 1 < SEQ) ? (t + 1) : t;
            const float* pp = g_preact + ((size_t)tn * BATCH + b0 + tb) * G4H + j0 + tj;
            nx0 = pp[0 * HID]; nx1 = pp[1 * HID]; nx2 = pp[2 * HID]; nx3 = pp[3 * HID];
        }

        ull acc2[8];
#pragma unroll
        for (int b = 0; b < 8; b++) acc2[b] = 0ull;
#pragma unroll
        for (int k4 = 0; k4 < 16; k4++) {
            const ull w0 = wp[k4 * 2 + 0], w1 = wp[k4 * 2 + 1];
#pragma unroll
            for (int b = 0; b < 8; b++) {
                ulonglong2 hv = *(const ulonglong2*)&hsf[b][kq * 64 + k4 * 4];
                acc2[b] = ffma2(hv.x, w0, acc2[b]);
                acc2[b] = ffma2(hv.y, w1, acc2[b]);
            }
        }
#pragma unroll
        for (int b = 0; b < 8; b++) {
            float lo, hi; upk2(acc2[b], lo, hi);
            reds[cmb * 33 + kq * 8 + b] = lo + hi;
        }
        __syncthreads();

        if (u < 128) {
            float p[4];
#pragma unroll
            for (int gg = 0; gg < 4; gg++) {
                int cc = gg * 16 + tj;
                p[gg] = reds[cc * 33 + 0 + tb] + reds[cc * 33 + 8 + tb]
                      + reds[cc * 33 + 16 + tb] + reds[cc * 33 + 24 + tb];
            }
            p[0] += px0; p[1] += px1; p[2] += px2; p[3] += px3;

            float it = sigf(p[0]);
            float ft = sigf(p[1]);
            float ot = sigf(p[2]);
            float gt = tanhf_(p[3]);
            cst = cst * ft + it * gt;
            float ht = ot * tanhf_(cst);
            hlast = ht;

            out[((size_t)t * BATCH + b0 + tb) * HID + j0 + tj] = ht;
            g_hbuf[(t + 1) & 1][(b0 + tb) * HID + j0 + tj] = ht;
        }
        __syncthreads();

        if (t < SEQ - 1) {
            if (u == 0) {
                __threadfence();
                atomicAdd(cnt, 1u);
                const unsigned target = (unsigned)(t + 1) * 16u;
                unsigned v;
                do {
                    asm volatile("ld.acquire.gpu.global.u32 %0, [%1];"
                                 : "=r"(v) : "l"(cnt) : "memory");
                } while (v < target);
            }
            __syncthreads();
        }
        px0 = nx0; px1 = nx1; px2 = nx2; px3 = nx3;
    }

    if (u < 128) {
        const size_t base = (size_t)SEQ * BATCH * HID;
        const int idx = (b0 + tb) * HID + j0 + tj;
        out[base + idx]               = hlast;
        out[base + BATCH * HID + idx] = cst;
    }
}

// ---------------------------------------------------------------------------
extern "C" void kernel_launch(void* const* d_in, const int* in_sizes, int n_in,
                              void* d_out, int out_size)
{
    const float* x  = (const float*)d_in[0];
    const float* h0 = (const float*)d_in[1];
    const float* c0 = (const float*)d_in[2];
    const float* Wi = (const float*)d_in[3];
    const float* bi = (const float*)d_in[4];
    const float* Wh = (const float*)d_in[5];
    const float* bh = (const float*)d_in[6];
    float* out = (float*)d_out;

    convert_x_kernel<<<8192, 256>>>(x);
    convert_w_kernel<<<256, 256>>>(Wi, bi, bh);

    dim3 gg(G4H / 128, MTOT / 128);
    gemm_mma_kernel<<<gg, 256>>>();

    cudaFuncSetAttribute(lstm_rec_cluster,
                         cudaFuncAttributeNonPortableClusterSizeAllowed, 1);

    cudaLaunchConfig_t cfg = {};
    cfg.gridDim  = dim3(128, 1, 1);
    cfg.blockDim = dim3(256, 1, 1);
    cfg.dynamicSmemBytes = 0;
    cfg.stream = 0;
    cudaLaunchAttribute at[1];
    at[0].id = cudaLaunchAttributeClusterDimension;
    at[0].val.clusterDim.x = 16;
    at[0].val.clusterDim.y = 1;
    at[0].val.clusterDim.z = 1;
    cfg.attrs = at;
    cfg.numAttrs = 1;

    int cs = 0;
    cudaLaunchConfig_t probe = {};
    probe.gridDim  = dim3(128, 1, 1);
    probe.blockDim = dim3(256, 1, 1);
    probe.dynamicSmemBytes = 0;
    cudaOccupancyMaxPotentialClusterSize(&cs, lstm_rec_cluster, &probe);

    if (cs >= 16) {
        cudaLaunchKernelEx(&cfg, lstm_rec_cluster, h0, c0, Wh, out);
    } else {
        lstm_rec_kernel<<<128, 256>>>(h0, c0, Wh, out);
    }
}

// round 13
// speedup vs baseline: 1.7460x; 1.7460x over previous
#include <cuda_runtime.h>
#include <cuda_bf16.h>
#include <cstdint>

typedef unsigned long long ull;

#define SEQ   2048
#define BATCH 64
#define KIN   256
#define HID   256
#define G4H   1024   // 4*HID
#define MTOT  (SEQ * BATCH)   // 131072

// ---------------- scratch (device globals; no allocation allowed) ----------
__device__ float g_preact[(size_t)SEQ * BATCH * G4H];          // 512 MB
__device__ __nv_bfloat16 g_xh[(size_t)MTOT * KIN];             // 64 MB
__device__ __nv_bfloat16 g_xl[(size_t)MTOT * KIN];             // 64 MB
__device__ __nv_bfloat16 g_wih[(size_t)G4H * KIN];
__device__ __nv_bfloat16 g_wil[(size_t)G4H * KIN];
__device__ float g_bias[G4H];
// tagged h exchange: [batch-slice][parity][b][j] = {u32 tag, f32 value} packed
__device__ ull g_hex[8][2][8][256];                            // 256 KB

// ---------------- small helpers -------------------------------------------
__device__ __forceinline__ uint32_t smem_u32(const void* p) {
    uint32_t a;
    asm("{ .reg .u64 t; cvta.to.shared.u64 t, %1; cvt.u32.u64 %0, t; }"
        : "=r"(a) : "l"(p));
    return a;
}
__device__ __forceinline__ ull ffma2(ull a, ull b, ull c) {
    ull d;
    asm("fma.rn.f32x2 %0, %1, %2, %3;" : "=l"(d) : "l"(a), "l"(b), "l"(c));
    return d;
}
__device__ __forceinline__ ull pk2(float x, float y) {
    ull r;
    asm("mov.b64 %0, {%1, %2};" : "=l"(r)
        : "r"(__float_as_uint(x)), "r"(__float_as_uint(y)));
    return r;
}
__device__ __forceinline__ void upk2(ull v, float& x, float& y) {
    uint32_t a, b;
    asm("mov.b64 {%0, %1}, %2;" : "=r"(a), "=r"(b) : "l"(v));
    x = __uint_as_float(a); y = __uint_as_float(b);
}
__device__ __forceinline__ float sigf(float x) {
    return __fdividef(1.f, 1.f + __expf(-x));
}
__device__ __forceinline__ float tanhf_(float x) { return 2.f * sigf(2.f * x) - 1.f; }

__device__ __forceinline__ void ldm_x4(uint32_t* r, uint32_t addr) {
    asm volatile("ldmatrix.sync.aligned.m8n8.x4.shared.b16 {%0,%1,%2,%3}, [%4];"
                 : "=r"(r[0]), "=r"(r[1]), "=r"(r[2]), "=r"(r[3]) : "r"(addr));
}
__device__ __forceinline__ void ldm_x2(uint32_t* r, uint32_t addr) {
    asm volatile("ldmatrix.sync.aligned.m8n8.x2.shared.b16 {%0,%1}, [%2];"
                 : "=r"(r[0]), "=r"(r[1]) : "r"(addr));
}
__device__ __forceinline__ void mma16816(float* d, const uint32_t* a,
                                         const uint32_t* b) {
    asm volatile(
        "mma.sync.aligned.m16n8k16.row.col.f32.bf16.bf16.f32 "
        "{%0,%1,%2,%3}, {%4,%5,%6,%7}, {%8,%9}, {%0,%1,%2,%3};"
        : "+f"(d[0]), "+f"(d[1]), "+f"(d[2]), "+f"(d[3])
        : "r"(a[0]), "r"(a[1]), "r"(a[2]), "r"(a[3]), "r"(b[0]), "r"(b[1]));
}

// tagged-word publish / poll primitives (plain L2-coherent relaxed ops)
__device__ __forceinline__ void st_rlx_u64(ull* p, ull v) {
    asm volatile("st.relaxed.gpu.global.u64 [%0], %1;" :: "l"(p), "l"(v)
                 : "memory");
}
__device__ __forceinline__ ulonglong2 ld_rlx_v2u64(const ull* p) {
    ulonglong2 v;
    asm volatile("ld.relaxed.gpu.global.v2.u64 {%0,%1}, [%2];"
                 : "=l"(v.x), "=l"(v.y) : "l"(p) : "memory");
    return v;
}

// ---------------------------------------------------------------------------
// Kernel 0a: convert x -> bf16 hi/lo planes
// ---------------------------------------------------------------------------
__global__ void __launch_bounds__(256) convert_x_kernel(const float* __restrict__ x)
{
    const size_t n4 = (size_t)MTOT * KIN / 4;
    for (size_t i = (size_t)blockIdx.x * blockDim.x + threadIdx.x; i < n4;
         i += (size_t)gridDim.x * blockDim.x) {
        float4 v = ((const float4*)x)[i];
        __nv_bfloat16 h0 = __float2bfloat16(v.x);
        __nv_bfloat16 h1 = __float2bfloat16(v.y);
        __nv_bfloat16 h2 = __float2bfloat16(v.z);
        __nv_bfloat16 h3 = __float2bfloat16(v.w);
        __nv_bfloat16 l0 = __float2bfloat16(v.x - __bfloat162float(h0));
        __nv_bfloat16 l1 = __float2bfloat16(v.y - __bfloat162float(h1));
        __nv_bfloat16 l2 = __float2bfloat16(v.z - __bfloat162float(h2));
        __nv_bfloat16 l3 = __float2bfloat16(v.w - __bfloat162float(h3));
        __nv_bfloat162 ph0 = {h0, h1}, ph1 = {h2, h3};
        __nv_bfloat162 pl0 = {l0, l1}, pl1 = {l2, l3};
        uint2 uh = {*(uint32_t*)&ph0, *(uint32_t*)&ph1};
        uint2 ul = {*(uint32_t*)&pl0, *(uint32_t*)&pl1};
        ((uint2*)g_xh)[i] = uh;
        ((uint2*)g_xl)[i] = ul;
    }
}

// ---------------------------------------------------------------------------
// Kernel 0b: convert Wi -> bf16 hi/lo, combine bias, clear exchange tags
// ---------------------------------------------------------------------------
__global__ void __launch_bounds__(256) convert_w_kernel(
    const float* __restrict__ Wi, const float* __restrict__ bi,
    const float* __restrict__ bh)
{
    const size_t tid = (size_t)blockIdx.x * blockDim.x + threadIdx.x;
    const size_t n4 = (size_t)G4H * KIN / 4;   // 65536
    if (tid < n4) {
        float4 v = ((const float4*)Wi)[tid];
        __nv_bfloat16 h0 = __float2bfloat16(v.x);
        __nv_bfloat16 h1 = __float2bfloat16(v.y);
        __nv_bfloat16 h2 = __float2bfloat16(v.z);
        __nv_bfloat16 h3 = __float2bfloat16(v.w);
        __nv_bfloat16 l0 = __float2bfloat16(v.x - __bfloat162float(h0));
        __nv_bfloat16 l1 = __float2bfloat16(v.y - __bfloat162float(h1));
        __nv_bfloat16 l2 = __float2bfloat16(v.z - __bfloat162float(h2));
        __nv_bfloat16 l3 = __float2bfloat16(v.w - __bfloat162float(h3));
        __nv_bfloat162 ph0 = {h0, h1}, ph1 = {h2, h3};
        __nv_bfloat162 pl0 = {l0, l1}, pl1 = {l2, l3};
        uint2 uh = {*(uint32_t*)&ph0, *(uint32_t*)&ph1};
        uint2 ul = {*(uint32_t*)&pl0, *(uint32_t*)&pl1};
        ((uint2*)g_wih)[tid] = uh;
        ((uint2*)g_wil)[tid] = ul;
    }
    if (tid < G4H) g_bias[tid] = bi[tid] + bh[tid];
    // clear h-exchange tags (must be re-done every launch for graph replays)
    if (tid < 8 * 2 * 8 * 256) ((ull*)g_hex)[tid] = 0ull;
}

// ---------------------------------------------------------------------------
// Kernel 1: bf16x3 GEMM via mma.sync.m16n8k16  (unchanged, known-good)
// ---------------------------------------------------------------------------
#define LDP 40

__global__ void __launch_bounds__(256) gemm_mma_kernel()
{
    __shared__ __nv_bfloat16 Ah[128][LDP], Al[128][LDP];
    __shared__ __nv_bfloat16 Bh[128][LDP], Bl[128][LDP];

    const int tid = threadIdx.x;
    const int w = tid >> 5, l = tid & 31;
    const int m0 = blockIdx.y * 128, n0 = blockIdx.x * 128;
    const int wm = w & 1;
    const int wn = w >> 1;

    float acc[4][4][4];
#pragma unroll
    for (int mi = 0; mi < 4; mi++)
#pragma unroll
        for (int ni = 0; ni < 4; ni++)
#pragma unroll
            for (int q = 0; q < 4; q++) acc[mi][ni][q] = 0.f;

    for (int kc = 0; kc < KIN; kc += 32) {
#pragma unroll
        for (int tb = 0; tb < 4; tb++) {
            const __nv_bfloat16* src =
                (tb == 0) ? g_xh : (tb == 1) ? g_xl : (tb == 2) ? g_wih : g_wil;
            const int row0 = (tb < 2) ? m0 : n0;
            __nv_bfloat16 (*dst)[LDP] =
                (tb == 0) ? Ah : (tb == 1) ? Al : (tb == 2) ? Bh : Bl;
#pragma unroll
            for (int i = tid; i < 512; i += 256) {
                int r = i >> 2, q = i & 3;
                uint4 v = *(const uint4*)(src + (size_t)(row0 + r) * KIN + kc + q * 8);
                *(uint2*)&dst[r][q * 8]     = make_uint2(v.x, v.y);
                *(uint2*)&dst[r][q * 8 + 4] = make_uint2(v.z, v.w);
            }
        }
        __syncthreads();

#pragma unroll
        for (int p = 0; p < 3; p++) {
            const __nv_bfloat16 (*Ap)[LDP] = (p == 2) ? Al : Ah;
            const __nv_bfloat16 (*Bp)[LDP] = (p == 1) ? Bl : Bh;
#pragma unroll
            for (int ks = 0; ks < 2; ks++) {
                uint32_t af[4][4], bf[4][2];
#pragma unroll
                for (int mi = 0; mi < 4; mi++)
                    ldm_x4(af[mi], smem_u32(
                        &Ap[wm * 64 + mi * 16 + (l & 15)][ks * 16 + (l >> 4) * 8]));
#pragma unroll
                for (int ni = 0; ni < 4; ni++)
                    ldm_x2(bf[ni], smem_u32(
                        &Bp[wn * 32 + ni * 8 + (l & 7)][ks * 16 + ((l >> 3) & 1) * 8]));
#pragma unroll
                for (int mi = 0; mi < 4; mi++)
#pragma unroll
                    for (int ni = 0; ni < 4; ni++)
                        mma16816(acc[mi][ni], af[mi], bf[ni]);
            }
        }
        __syncthreads();
    }

#pragma unroll
    for (int ni = 0; ni < 4; ni++) {
        const int gn = n0 + wn * 32 + ni * 8 + (l & 3) * 2;
        const float b0 = g_bias[gn], b1 = g_bias[gn + 1];
#pragma unroll
        for (int mi = 0; mi < 4; mi++) {
            const int gm = m0 + wm * 64 + mi * 16 + (l >> 2);
            float2 v0 = {acc[mi][ni][0] + b0, acc[mi][ni][1] + b1};
            float2 v1 = {acc[mi][ni][2] + b0, acc[mi][ni][3] + b1};
            *(float2*)&g_preact[(size_t)gm * G4H + gn]       = v0;
            *(float2*)&g_preact[(size_t)(gm + 8) * G4H + gn] = v1;
        }
    }
}

// ---------------------------------------------------------------------------
// Kernel 2: recurrent kernel with TAGGED-VALUE POLLING (no barrier, no fence).
// 128 blocks = 16 j-slices x 8 batch-slices.
// Publish: each (b,j) owner stores one 8B {tag,val} word, st.relaxed.gpu.
// Consume: warp pair (kq) polls exactly its k-quarter's 512 words with
// ld.relaxed.gpu.v2.u64, fills its hs quarter, pair-syncs on named barrier,
// then starts its GEMM slice immediately (absorbs inter-block skew).
// ---------------------------------------------------------------------------
__global__ void __launch_bounds__(256, 1) lstm_rec_poll(
    const float* __restrict__ h0, const float* __restrict__ c0,
    const float* __restrict__ Wh, float* __restrict__ out)
{
    __shared__ float hs[8][256];        // h tile (b, j)
    __shared__ float reds[64 * 33];

    const int u   = threadIdx.x;
    const int jb  = blockIdx.x & 15;
    const int bb  = blockIdx.x >> 4;
    const int j0  = jb * 16;
    const int b0  = bb * 8;

    const int wid = u >> 5;
    const int l   = u & 31;
    const int ch  = wid >> 2;           // pair half 0/1
    const int kq  = wid & 3;            // k quarter (64 k each)
    const int cmb = ch * 32 + l;        // (gate, local j)
    const int g   = cmb >> 4;
    const int jj  = cmb & 15;

    // poll assignment: this thread owns 8 consecutive j of one batch row
    const int pb = ch * 4 + (l >> 3);           // batch row 0..7
    const int pj = kq * 64 + (l & 7) * 8;       // j base within quarter

    // weights: 64 per thread, packed as f32x2 pairs
    ull wp[32];
    {
        const float* wrow = Wh + (size_t)(g * HID + j0 + jj) * HID + kq * 64;
#pragma unroll
        for (int q = 0; q < 16; q++) {
            float4 v = *(const float4*)&wrow[q * 4];
            wp[q * 2 + 0] = pk2(v.x, v.y);
            wp[q * 2 + 1] = pk2(v.z, v.w);
        }
    }

    const int tb = u >> 4;
    const int tj = u & 15;
    float cst = 0.f, hlast = 0.f;
    if (u < 128) cst = c0[(b0 + tb) * HID + j0 + tj];

    // preload h0 (t = 0 consumes it directly; no tags involved)
#pragma unroll
    for (int q = 0; q < 2; q++) {
        int f  = u * 2 + q;
        int b  = f >> 6;
        int ko = (f & 63) * 4;
        *(float4*)&hs[b][ko] = *(const float4*)&h0[(size_t)(b0 + b) * HID + ko];
    }

    // preact for t=0
    float px0 = 0.f, px1 = 0.f, px2 = 0.f, px3 = 0.f;
    if (u < 128) {
        const float* pp = g_preact + ((size_t)(b0 + tb)) * G4H + j0 + tj;
        px0 = pp[0 * HID]; px1 = pp[1 * HID]; px2 = pp[2 * HID]; px3 = pp[3 * HID];
    }
    __syncthreads();

    for (int t = 0; t < SEQ; t++) {
        if (t > 0) {
            // ---- per-warp poll of this quarter's 8 tagged words -------
            const ull* p = &g_hex[bb][t & 1][pb][pj];
            const uint32_t tg = (uint32_t)t;
            ulonglong2 v0, v1, v2, v3;
            while (true) {
                v0 = ld_rlx_v2u64(p + 0);
                v1 = ld_rlx_v2u64(p + 2);
                v2 = ld_rlx_v2u64(p + 4);
                v3 = ld_rlx_v2u64(p + 6);
                bool ok = ((uint32_t)(v0.x >> 32) == tg) &
                          ((uint32_t)(v0.y >> 32) == tg) &
                          ((uint32_t)(v1.x >> 32) == tg) &
                          ((uint32_t)(v1.y >> 32) == tg) &
                          ((uint32_t)(v2.x >> 32) == tg) &
                          ((uint32_t)(v2.y >> 32) == tg) &
                          ((uint32_t)(v3.x >> 32) == tg) &
                          ((uint32_t)(v3.y >> 32) == tg);
                if (ok) break;
            }
            float2 f0 = {__uint_as_float((uint32_t)v0.x),
                         __uint_as_float((uint32_t)v0.y)};
            float2 f1 = {__uint_as_float((uint32_t)v1.x),
                         __uint_as_float((uint32_t)v1.y)};
            float2 f2 = {__uint_as_float((uint32_t)v2.x),
                         __uint_as_float((uint32_t)v2.y)};
            float2 f3 = {__uint_as_float((uint32_t)v3.x),
                         __uint_as_float((uint32_t)v3.y)};
            *(float2*)&hs[pb][pj + 0] = f0;
            *(float2*)&hs[pb][pj + 2] = f1;
            *(float2*)&hs[pb][pj + 4] = f2;
            *(float2*)&hs[pb][pj + 6] = f3;
            // pair sync: warps kq and kq+4 produced this quarter together
            asm volatile("bar.sync %0, 64;" :: "r"(kq + 1) : "memory");
        }

        // prefetch preact t+1
        float nx0 = 0.f, nx1 = 0.f, nx2 = 0.f, nx3 = 0.f;
        if (u < 128) {
            int tn = (t + 1 < SEQ) ? (t + 1) : t;
            const float* pp = g_preact + ((size_t)tn * BATCH + b0 + tb) * G4H + j0 + tj;
            nx0 = pp[0 * HID]; nx1 = pp[1 * HID]; nx2 = pp[2 * HID]; nx3 = pp[3 * HID];
        }

        // packed-f32x2 GEMM over this thread's k-quarter
        ull acc2[8];
#pragma unroll
        for (int b = 0; b < 8; b++) acc2[b] = 0ull;
#pragma unroll
        for (int k4 = 0; k4 < 16; k4++) {
            const ull w0 = wp[k4 * 2 + 0], w1 = wp[k4 * 2 + 1];
#pragma unroll
            for (int b = 0; b < 8; b++) {
                ulonglong2 hv = *(const ulonglong2*)&hs[b][kq * 64 + k4 * 4];
                acc2[b] = ffma2(hv.x, w0, acc2[b]);
                acc2[b] = ffma2(hv.y, w1, acc2[b]);
            }
        }
#pragma unroll
        for (int b = 0; b < 8; b++) {
            float lo, hi; upk2(acc2[b], lo, hi);
            reds[cmb * 33 + kq * 8 + b] = lo + hi;
        }
        __syncthreads();

        if (u < 128) {
            float p[4];
#pragma unroll
            for (int gg = 0; gg < 4; gg++) {
                int cc = gg * 16 + tj;
                p[gg] = reds[cc * 33 + 0 + tb] + reds[cc * 33 + 8 + tb]
                      + reds[cc * 33 + 16 + tb] + reds[cc * 33 + 24 + tb];
            }
            p[0] += px0; p[1] += px1; p[2] += px2; p[3] += px3;

            float it = sigf(p[0]);
            float ft = sigf(p[1]);
            float ot = sigf(p[2]);
            float gt = tanhf_(p[3]);
            cst = cst * ft + it * gt;
            float ht = ot * tanhf_(cst);
            hlast = ht;

            // publish FIRST (critical path for peers), then local output
            if (t < SEQ - 1) {
                ull pub = ((ull)(uint32_t)(t + 1) << 32)
                        | (ull)__float_as_uint(ht);
                st_rlx_u64(&g_hex[bb][(t + 1) & 1][tb][j0 + tj], pub);
            }
            out[((size_t)t * BATCH + b0 + tb) * HID + j0 + tj] = ht;
        }
        __syncthreads();   // protect reds (and hs) against fast-warp overwrite

        px0 = nx0; px1 = nx1; px2 = nx2; px3 = nx3;
    }

    if (u < 128) {
        const size_t base = (size_t)SEQ * BATCH * HID;
        const int idx = (b0 + tb) * HID + j0 + tj;
        out[base + idx]               = hlast;
        out[base + BATCH * HID + idx] = cst;
    }
}

// ---------------------------------------------------------------------------
extern "C" void kernel_launch(void* const* d_in, const int* in_sizes, int n_in,
                              void* d_out, int out_size)
{
    const float* x  = (const float*)d_in[0];
    const float* h0 = (const float*)d_in[1];
    const float* c0 = (const float*)d_in[2];
    const float* Wi = (const float*)d_in[3];
    const float* bi = (const float*)d_in[4];
    const float* Wh = (const float*)d_in[5];
    const float* bh = (const float*)d_in[6];
    float* out = (float*)d_out;

    convert_x_kernel<<<8192, 256>>>(x);
    convert_w_kernel<<<256, 256>>>(Wi, bi, bh);

    dim3 gg(G4H / 128, MTOT / 128);
    gemm_mma_kernel<<<gg, 256>>>();

    lstm_rec_poll<<<128, 256>>>(h0, c0, Wh, out);
}

// round 14
// speedup vs baseline: 1.8213x; 1.0432x over previous
#include <cuda_runtime.h>
#include <cuda_bf16.h>
#include <cstdint>

typedef unsigned long long ull;

#define SEQ   2048
#define BATCH 64
#define KIN   256
#define HID   256
#define G4H   1024   // 4*HID
#define MTOT  (SEQ * BATCH)   // 131072

// ---------------- scratch (device globals; no allocation allowed) ----------
__device__ float g_preact[(size_t)SEQ * BATCH * G4H];          // 512 MB
__device__ __nv_bfloat16 g_xh[(size_t)MTOT * KIN];             // 64 MB
__device__ __nv_bfloat16 g_xl[(size_t)MTOT * KIN];             // 64 MB
__device__ __nv_bfloat16 g_wih[(size_t)G4H * KIN];
__device__ __nv_bfloat16 g_wil[(size_t)G4H * KIN];
__device__ float g_bias[G4H];
// tagged h exchange: [batch-slice][parity][b][j] = {u32 tag, f32 value} packed
__device__ ull g_hex[8][2][8][256];                            // 256 KB

// ---------------- small helpers -------------------------------------------
__device__ __forceinline__ uint32_t smem_u32(const void* p) {
    uint32_t a;
    asm("{ .reg .u64 t; cvta.to.shared.u64 t, %1; cvt.u32.u64 %0, t; }"
        : "=r"(a) : "l"(p));
    return a;
}
__device__ __forceinline__ ull ffma2(ull a, ull b, ull c) {
    ull d;
    asm("fma.rn.f32x2 %0, %1, %2, %3;" : "=l"(d) : "l"(a), "l"(b), "l"(c));
    return d;
}
__device__ __forceinline__ ull pk2(float x, float y) {
    ull r;
    asm("mov.b64 %0, {%1, %2};" : "=l"(r)
        : "r"(__float_as_uint(x)), "r"(__float_as_uint(y)));
    return r;
}
__device__ __forceinline__ void upk2(ull v, float& x, float& y) {
    uint32_t a, b;
    asm("mov.b64 {%0, %1}, %2;" : "=r"(a), "=r"(b) : "l"(v));
    x = __uint_as_float(a); y = __uint_as_float(b);
}
__device__ __forceinline__ float sigf(float x) {
    return __fdividef(1.f, 1.f + __expf(-x));
}
__device__ __forceinline__ float tanhf_(float x) { return 2.f * sigf(2.f * x) - 1.f; }

__device__ __forceinline__ void ldm_x4(uint32_t* r, uint32_t addr) {
    asm volatile("ldmatrix.sync.aligned.m8n8.x4.shared.b16 {%0,%1,%2,%3}, [%4];"
                 : "=r"(r[0]), "=r"(r[1]), "=r"(r[2]), "=r"(r[3]) : "r"(addr));
}
__device__ __forceinline__ void ldm_x2(uint32_t* r, uint32_t addr) {
    asm volatile("ldmatrix.sync.aligned.m8n8.x2.shared.b16 {%0,%1}, [%2];"
                 : "=r"(r[0]), "=r"(r[1]) : "r"(addr));
}
__device__ __forceinline__ void mma16816(float* d, const uint32_t* a,
                                         const uint32_t* b) {
    asm volatile(
        "mma.sync.aligned.m16n8k16.row.col.f32.bf16.bf16.f32 "
        "{%0,%1,%2,%3}, {%4,%5,%6,%7}, {%8,%9}, {%0,%1,%2,%3};"
        : "+f"(d[0]), "+f"(d[1]), "+f"(d[2]), "+f"(d[3])
        : "r"(a[0]), "r"(a[1]), "r"(a[2]), "r"(a[3]), "r"(b[0]), "r"(b[1]));
}

// tagged-word publish / poll primitives (plain L2-coherent relaxed ops)
__device__ __forceinline__ void st_rlx_u64(ull* p, ull v) {
    asm volatile("st.relaxed.gpu.global.u64 [%0], %1;" :: "l"(p), "l"(v)
                 : "memory");
}
__device__ __forceinline__ ulonglong2 ld_rlx_v2u64(const ull* p) {
    ulonglong2 v;
    asm volatile("ld.relaxed.gpu.global.v2.u64 {%0,%1}, [%2];"
                 : "=l"(v.x), "=l"(v.y) : "l"(p) : "memory");
    return v;
}

// ---------------------------------------------------------------------------
// Kernel 0a: convert x -> bf16 hi/lo planes
// ---------------------------------------------------------------------------
__global__ void __launch_bounds__(256) convert_x_kernel(const float* __restrict__ x)
{
    const size_t n4 = (size_t)MTOT * KIN / 4;
    for (size_t i = (size_t)blockIdx.x * blockDim.x + threadIdx.x; i < n4;
         i += (size_t)gridDim.x * blockDim.x) {
        float4 v = ((const float4*)x)[i];
        __nv_bfloat16 h0 = __float2bfloat16(v.x);
        __nv_bfloat16 h1 = __float2bfloat16(v.y);
        __nv_bfloat16 h2 = __float2bfloat16(v.z);
        __nv_bfloat16 h3 = __float2bfloat16(v.w);
        __nv_bfloat16 l0 = __float2bfloat16(v.x - __bfloat162float(h0));
        __nv_bfloat16 l1 = __float2bfloat16(v.y - __bfloat162float(h1));
        __nv_bfloat16 l2 = __float2bfloat16(v.z - __bfloat162float(h2));
        __nv_bfloat16 l3 = __float2bfloat16(v.w - __bfloat162float(h3));
        __nv_bfloat162 ph0 = {h0, h1}, ph1 = {h2, h3};
        __nv_bfloat162 pl0 = {l0, l1}, pl1 = {l2, l3};
        uint2 uh = {*(uint32_t*)&ph0, *(uint32_t*)&ph1};
        uint2 ul = {*(uint32_t*)&pl0, *(uint32_t*)&pl1};
        ((uint2*)g_xh)[i] = uh;
        ((uint2*)g_xl)[i] = ul;
    }
}

// ---------------------------------------------------------------------------
// Kernel 0b: convert Wi -> bf16 hi/lo, combine bias, clear exchange tags
// ---------------------------------------------------------------------------
__global__ void __launch_bounds__(256) convert_w_kernel(
    const float* __restrict__ Wi, const float* __restrict__ bi,
    const float* __restrict__ bh)
{
    const size_t tid = (size_t)blockIdx.x * blockDim.x + threadIdx.x;
    const size_t n4 = (size_t)G4H * KIN / 4;   // 65536
    if (tid < n4) {
        float4 v = ((const float4*)Wi)[tid];
        __nv_bfloat16 h0 = __float2bfloat16(v.x);
        __nv_bfloat16 h1 = __float2bfloat16(v.y);
        __nv_bfloat16 h2 = __float2bfloat16(v.z);
        __nv_bfloat16 h3 = __float2bfloat16(v.w);
        __nv_bfloat16 l0 = __float2bfloat16(v.x - __bfloat162float(h0));
        __nv_bfloat16 l1 = __float2bfloat16(v.y - __bfloat162float(h1));
        __nv_bfloat16 l2 = __float2bfloat16(v.z - __bfloat162float(h2));
        __nv_bfloat16 l3 = __float2bfloat16(v.w - __bfloat162float(h3));
        __nv_bfloat162 ph0 = {h0, h1}, ph1 = {h2, h3};
        __nv_bfloat162 pl0 = {l0, l1}, pl1 = {l2, l3};
        uint2 uh = {*(uint32_t*)&ph0, *(uint32_t*)&ph1};
        uint2 ul = {*(uint32_t*)&pl0, *(uint32_t*)&pl1};
        ((uint2*)g_wih)[tid] = uh;
        ((uint2*)g_wil)[tid] = ul;
    }
    if (tid < G4H) g_bias[tid] = bi[tid] + bh[tid];
    // clear h-exchange tags (must be re-done every launch for graph replays)
    if (tid < 8 * 2 * 8 * 256) ((ull*)g_hex)[tid] = 0ull;
}

// ---------------------------------------------------------------------------
// Kernel 1: bf16x3 GEMM via mma.sync.m16n8k16  (unchanged, known-good)
// ---------------------------------------------------------------------------
#define LDP 40

__global__ void __launch_bounds__(256) gemm_mma_kernel()
{
    __shared__ __nv_bfloat16 Ah[128][LDP], Al[128][LDP];
    __shared__ __nv_bfloat16 Bh[128][LDP], Bl[128][LDP];

    const int tid = threadIdx.x;
    const int w = tid >> 5, l = tid & 31;
    const int m0 = blockIdx.y * 128, n0 = blockIdx.x * 128;
    const int wm = w & 1;
    const int wn = w >> 1;

    float acc[4][4][4];
#pragma unroll
    for (int mi = 0; mi < 4; mi++)
#pragma unroll
        for (int ni = 0; ni < 4; ni++)
#pragma unroll
            for (int q = 0; q < 4; q++) acc[mi][ni][q] = 0.f;

    for (int kc = 0; kc < KIN; kc += 32) {
#pragma unroll
        for (int tb = 0; tb < 4; tb++) {
            const __nv_bfloat16* src =
                (tb == 0) ? g_xh : (tb == 1) ? g_xl : (tb == 2) ? g_wih : g_wil;
            const int row0 = (tb < 2) ? m0 : n0;
            __nv_bfloat16 (*dst)[LDP] =
                (tb == 0) ? Ah : (tb == 1) ? Al : (tb == 2) ? Bh : Bl;
#pragma unroll
            for (int i = tid; i < 512; i += 256) {
                int r = i >> 2, q = i & 3;
                uint4 v = *(const uint4*)(src + (size_t)(row0 + r) * KIN + kc + q * 8);
                *(uint2*)&dst[r][q * 8]     = make_uint2(v.x, v.y);
                *(uint2*)&dst[r][q * 8 + 4] = make_uint2(v.z, v.w);
            }
        }
        __syncthreads();

#pragma unroll
        for (int p = 0; p < 3; p++) {
            const __nv_bfloat16 (*Ap)[LDP] = (p == 2) ? Al : Ah;
            const __nv_bfloat16 (*Bp)[LDP] = (p == 1) ? Bl : Bh;
#pragma unroll
            for (int ks = 0; ks < 2; ks++) {
                uint32_t af[4][4], bf[4][2];
#pragma unroll
                for (int mi = 0; mi < 4; mi++)
                    ldm_x4(af[mi], smem_u32(
                        &Ap[wm * 64 + mi * 16 + (l & 15)][ks * 16 + (l >> 4) * 8]));
#pragma unroll
                for (int ni = 0; ni < 4; ni++)
                    ldm_x2(bf[ni], smem_u32(
                        &Bp[wn * 32 + ni * 8 + (l & 7)][ks * 16 + ((l >> 3) & 1) * 8]));
#pragma unroll
                for (int mi = 0; mi < 4; mi++)
#pragma unroll
                    for (int ni = 0; ni < 4; ni++)
                        mma16816(acc[mi][ni], af[mi], bf[ni]);
            }
        }
        __syncthreads();
    }

#pragma unroll
    for (int ni = 0; ni < 4; ni++) {
        const int gn = n0 + wn * 32 + ni * 8 + (l & 3) * 2;
        const float b0 = g_bias[gn], b1 = g_bias[gn + 1];
#pragma unroll
        for (int mi = 0; mi < 4; mi++) {
            const int gm = m0 + wm * 64 + mi * 16 + (l >> 2);
            float2 v0 = {acc[mi][ni][0] + b0, acc[mi][ni][1] + b1};
            float2 v1 = {acc[mi][ni][2] + b0, acc[mi][ni][3] + b1};
            *(float2*)&g_preact[(size_t)gm * G4H + gn]       = v0;
            *(float2*)&g_preact[(size_t)(gm + 8) * G4H + gn] = v1;
        }
    }
}

// ---------------------------------------------------------------------------
// Kernel 2: recurrent kernel with TAGGED-VALUE POLLING (no barrier, no fence).
// 128 blocks = 16 j-slices x 8 batch-slices.
// Publish: each (b,j) owner stores one 8B {tag,val} word, st.relaxed.gpu.
// Consume: warp pair (kq) polls exactly its k-quarter's 512 words with
// ld.relaxed.gpu.v2.u64, fills its hs quarter, pair-syncs on named barrier,
// then starts its GEMM slice immediately (absorbs inter-block skew).
// ---------------------------------------------------------------------------
__global__ void __launch_bounds__(256, 1) lstm_rec_poll(
    const float* __restrict__ h0, const float* __restrict__ c0,
    const float* __restrict__ Wh, float* __restrict__ out)
{
    __shared__ float hs[8][256];        // h tile (b, j)
    __shared__ float reds[64 * 33];

    const int u   = threadIdx.x;
    const int jb  = blockIdx.x & 15;
    const int bb  = blockIdx.x >> 4;
    const int j0  = jb * 16;
    const int b0  = bb * 8;

    const int wid = u >> 5;
    const int l   = u & 31;
    const int ch  = wid >> 2;           // pair half 0/1
    const int kq  = wid & 3;            // k quarter (64 k each)
    const int cmb = ch * 32 + l;        // (gate, local j)
    const int g   = cmb >> 4;
    const int jj  = cmb & 15;

    // poll assignment: this thread owns 8 consecutive j of one batch row
    const int pb = ch * 4 + (l >> 3);           // batch row 0..7
    const int pj = kq * 64 + (l & 7) * 8;       // j base within quarter

    // weights: 64 per thread, packed as f32x2 pairs
    ull wp[32];
    {
        const float* wrow = Wh + (size_t)(g * HID + j0 + jj) * HID + kq * 64;
#pragma unroll
        for (int q = 0; q < 16; q++) {
            float4 v = *(const float4*)&wrow[q * 4];
            wp[q * 2 + 0] = pk2(v.x, v.y);
            wp[q * 2 + 1] = pk2(v.z, v.w);
        }
    }

    const int tb = u >> 4;
    const int tj = u & 15;
    float cst = 0.f, hlast = 0.f;
    if (u < 128) cst = c0[(b0 + tb) * HID + j0 + tj];

    // preload h0 (t = 0 consumes it directly; no tags involved)
#pragma unroll
    for (int q = 0; q < 2; q++) {
        int f  = u * 2 + q;
        int b  = f >> 6;
        int ko = (f & 63) * 4;
        *(float4*)&hs[b][ko] = *(const float4*)&h0[(size_t)(b0 + b) * HID + ko];
    }

    // preact for t=0
    float px0 = 0.f, px1 = 0.f, px2 = 0.f, px3 = 0.f;
    if (u < 128) {
        const float* pp = g_preact + ((size_t)(b0 + tb)) * G4H + j0 + tj;
        px0 = pp[0 * HID]; px1 = pp[1 * HID]; px2 = pp[2 * HID]; px3 = pp[3 * HID];
    }
    __syncthreads();

    for (int t = 0; t < SEQ; t++) {
        if (t > 0) {
            // ---- per-warp poll of this quarter's 8 tagged words -------
            const ull* p = &g_hex[bb][t & 1][pb][pj];
            const uint32_t tg = (uint32_t)t;
            ulonglong2 v0, v1, v2, v3;
            while (true) {
                v0 = ld_rlx_v2u64(p + 0);
                v1 = ld_rlx_v2u64(p + 2);
                v2 = ld_rlx_v2u64(p + 4);
                v3 = ld_rlx_v2u64(p + 6);
                bool ok = ((uint32_t)(v0.x >> 32) == tg) &
                          ((uint32_t)(v0.y >> 32) == tg) &
                          ((uint32_t)(v1.x >> 32) == tg) &
                          ((uint32_t)(v1.y >> 32) == tg) &
                          ((uint32_t)(v2.x >> 32) == tg) &
                          ((uint32_t)(v2.y >> 32) == tg) &
                          ((uint32_t)(v3.x >> 32) == tg) &
                          ((uint32_t)(v3.y >> 32) == tg);
                if (ok) break;
            }
            float2 f0 = {__uint_as_float((uint32_t)v0.x),
                         __uint_as_float((uint32_t)v0.y)};
            float2 f1 = {__uint_as_float((uint32_t)v1.x),
                         __uint_as_float((uint32_t)v1.y)};
            float2 f2 = {__uint_as_float((uint32_t)v2.x),
                         __uint_as_float((uint32_t)v2.y)};
            float2 f3 = {__uint_as_float((uint32_t)v3.x),
                         __uint_as_float((uint32_t)v3.y)};
            *(float2*)&hs[pb][pj + 0] = f0;
            *(float2*)&hs[pb][pj + 2] = f1;
            *(float2*)&hs[pb][pj + 4] = f2;
            *(float2*)&hs[pb][pj + 6] = f3;
            // pair sync: warps kq and kq+4 produced this quarter together
            asm volatile("bar.sync %0, 64;" :: "r"(kq + 1) : "memory");
        }

        // prefetch preact t+1
        float nx0 = 0.f, nx1 = 0.f, nx2 = 0.f, nx3 = 0.f;
        if (u < 128) {
            int tn = (t + 1 < SEQ) ? (t + 1) : t;
            const float* pp = g_preact + ((size_t)tn * BATCH + b0 + tb) * G4H + j0 + tj;
            nx0 = pp[0 * HID]; nx1 = pp[1 * HID]; nx2 = pp[2 * HID]; nx3 = pp[3 * HID];
        }

        // packed-f32x2 GEMM over this thread's k-quarter
        ull acc2[8];
#pragma unroll
        for (int b = 0; b < 8; b++) acc2[b] = 0ull;
#pragma unroll
        for (int k4 = 0; k4 < 16; k4++) {
            const ull w0 = wp[k4 * 2 + 0], w1 = wp[k4 * 2 + 1];
#pragma unroll
            for (int b = 0; b < 8; b++) {
                ulonglong2 hv = *(const ulonglong2*)&hs[b][kq * 64 + k4 * 4];
                acc2[b] = ffma2(hv.x, w0, acc2[b]);
                acc2[b] = ffma2(hv.y, w1, acc2[b]);
            }
        }
#pragma unroll
        for (int b = 0; b < 8; b++) {
            float lo, hi; upk2(acc2[b], lo, hi);
            reds[cmb * 33 + kq * 8 + b] = lo + hi;
        }
        __syncthreads();

        if (u < 128) {
            float p[4];
#pragma unroll
            for (int gg = 0; gg < 4; gg++) {
                int cc = gg * 16 + tj;
                p[gg] = reds[cc * 33 + 0 + tb] + reds[cc * 33 + 8 + tb]
                      + reds[cc * 33 + 16 + tb] + reds[cc * 33 + 24 + tb];
            }
            p[0] += px0; p[1] += px1; p[2] += px2; p[3] += px3;

            float it = sigf(p[0]);
            float ft = sigf(p[1]);
            float ot = sigf(p[2]);
            float gt = tanhf_(p[3]);
            cst = cst * ft + it * gt;
            float ht = ot * tanhf_(cst);
            hlast = ht;

            // publish FIRST (critical path for peers), then local output
            if (t < SEQ - 1) {
                ull pub = ((ull)(uint32_t)(t + 1) << 32)
                        | (ull)__float_as_uint(ht);
                st_rlx_u64(&g_hex[bb][(t + 1) & 1][tb][j0 + tj], pub);
            }
            out[((size_t)t * BATCH + b0 + tb) * HID + j0 + tj] = ht;
        }
        __syncthreads();   // protect reds (and hs) against fast-warp overwrite

        px0 = nx0; px1 = nx1; px2 = nx2; px3 = nx3;
    }

    if (u < 128) {
        const size_t base = (size_t)SEQ * BATCH * HID;
        const int idx = (b0 + tb) * HID + j0 + tj;
        out[base + idx]               = hlast;
        out[base + BATCH * HID + idx] = cst;
    }
}

// ---------------------------------------------------------------------------
extern "C" void kernel_launch(void* const* d_in, const int* in_sizes, int n_in,
                              void* d_out, int out_size)
{
    const float* x  = (const float*)d_in[0];
    const float* h0 = (const float*)d_in[1];
    const float* c0 = (const float*)d_in[2];
    const float* Wi = (const float*)d_in[3];
    const float* bi = (const float*)d_in[4];
    const float* Wh = (const float*)d_in[5];
    const float* bh = (const float*)d_in[6];
    float* out = (float*)d_out;

    convert_x_kernel<<<8192, 256>>>(x);
    convert_w_kernel<<<256, 256>>>(Wi, bi, bh);

    dim3 gg(G4H / 128, MTOT / 128);
    gemm_mma_kernel<<<gg, 256>>>();

    lstm_rec_poll<<<128, 256>>>(h0, c0, Wh, out);
}

// round 15
// speedup vs baseline: 2.3418x; 1.2858x over previous
#include <cuda_runtime.h>
#include <cuda_bf16.h>
#include <cstdint>

typedef unsigned long long ull;

#define SEQ   2048
#define BATCH 64
#define KIN   256
#define HID   256
#define G4H   1024   // 4*HID
#define MTOT  (SEQ * BATCH)   // 131072

// ---------------- scratch (device globals; no allocation allowed) ----------
__device__ float g_preact[(size_t)SEQ * BATCH * G4H];          // 512 MB
__device__ __nv_bfloat16 g_xh[(size_t)MTOT * KIN];             // 64 MB
__device__ __nv_bfloat16 g_xl[(size_t)MTOT * KIN];             // 64 MB
__device__ __nv_bfloat16 g_wih[(size_t)G4H * KIN];
__device__ __nv_bfloat16 g_wil[(size_t)G4H * KIN];
__device__ float g_bias[G4H];
// tagged h exchange: [batch-slice][parity][b][j] = {u32 tag, f32 value} packed
__device__ __align__(16) ull g_hex[8][2][8][256];              // 256 KB

// ---------------- small helpers -------------------------------------------
__device__ __forceinline__ uint32_t smem_u32(const void* p) {
    uint32_t a;
    asm("{ .reg .u64 t; cvta.to.shared.u64 t, %1; cvt.u32.u64 %0, t; }"
        : "=r"(a) : "l"(p));
    return a;
}
__device__ __forceinline__ float sigf(float x) {
    return __fdividef(1.f, 1.f + __expf(-x));
}
__device__ __forceinline__ float tanhf_(float x) { return 2.f * sigf(2.f * x) - 1.f; }

__device__ __forceinline__ void ldm_x4(uint32_t* r, uint32_t addr) {
    asm volatile("ldmatrix.sync.aligned.m8n8.x4.shared.b16 {%0,%1,%2,%3}, [%4];"
                 : "=r"(r[0]), "=r"(r[1]), "=r"(r[2]), "=r"(r[3]) : "r"(addr));
}
__device__ __forceinline__ void ldm_x2(uint32_t* r, uint32_t addr) {
    asm volatile("ldmatrix.sync.aligned.m8n8.x2.shared.b16 {%0,%1}, [%2];"
                 : "=r"(r[0]), "=r"(r[1]) : "r"(addr));
}
__device__ __forceinline__ void mma16816(float* d, const uint32_t* a,
                                         const uint32_t* b) {
    asm volatile(
        "mma.sync.aligned.m16n8k16.row.col.f32.bf16.bf16.f32 "
        "{%0,%1,%2,%3}, {%4,%5,%6,%7}, {%8,%9}, {%0,%1,%2,%3};"
        : "+f"(d[0]), "+f"(d[1]), "+f"(d[2]), "+f"(d[3])
        : "r"(a[0]), "r"(a[1]), "r"(a[2]), "r"(a[3]), "r"(b[0]), "r"(b[1]));
}

// tagged-word publish / poll primitives (plain L2-coherent relaxed ops)
__device__ __forceinline__ void st_rlx_u64(ull* p, ull v) {
    asm volatile("st.relaxed.gpu.global.u64 [%0], %1;" :: "l"(p), "l"(v)
                 : "memory");
}
__device__ __forceinline__ ulonglong2 ld_rlx_v2u64(const ull* p) {
    ulonglong2 v;
    asm volatile("ld.relaxed.gpu.global.v2.u64 {%0,%1}, [%2];"
                 : "=l"(v.x), "=l"(v.y) : "l"(p) : "memory");
    return v;
}

// bf16 hi/lo split of a float
__device__ __forceinline__ void bsplit(float v, __nv_bfloat16& h, __nv_bfloat16& l) {
    h = __float2bfloat16(v);
    l = __float2bfloat16(v - __bfloat162float(h));
}

// ---------------------------------------------------------------------------
// Kernel 0a: convert x -> bf16 hi/lo planes
// ---------------------------------------------------------------------------
__global__ void __launch_bounds__(256) convert_x_kernel(const float* __restrict__ x)
{
    const size_t n4 = (size_t)MTOT * KIN / 4;
    for (size_t i = (size_t)blockIdx.x * blockDim.x + threadIdx.x; i < n4;
         i += (size_t)gridDim.x * blockDim.x) {
        float4 v = ((const float4*)x)[i];
        __nv_bfloat16 h0, h1, h2, h3, l0, l1, l2, l3;
        bsplit(v.x, h0, l0); bsplit(v.y, h1, l1);
        bsplit(v.z, h2, l2); bsplit(v.w, h3, l3);
        __nv_bfloat162 ph0 = {h0, h1}, ph1 = {h2, h3};
        __nv_bfloat162 pl0 = {l0, l1}, pl1 = {l2, l3};
        uint2 uh = {*(uint32_t*)&ph0, *(uint32_t*)&ph1};
        uint2 ul = {*(uint32_t*)&pl0, *(uint32_t*)&pl1};
        ((uint2*)g_xh)[i] = uh;
        ((uint2*)g_xl)[i] = ul;
    }
}

// ---------------------------------------------------------------------------
// Kernel 0b: convert Wi -> bf16 hi/lo, combine bias, clear exchange tags
// ---------------------------------------------------------------------------
__global__ void __launch_bounds__(256) convert_w_kernel(
    const float* __restrict__ Wi, const float* __restrict__ bi,
    const float* __restrict__ bh)
{
    const size_t tid = (size_t)blockIdx.x * blockDim.x + threadIdx.x;
    const size_t n4 = (size_t)G4H * KIN / 4;   // 65536
    if (tid < n4) {
        float4 v = ((const float4*)Wi)[tid];
        __nv_bfloat16 h0, h1, h2, h3, l0, l1, l2, l3;
        bsplit(v.x, h0, l0); bsplit(v.y, h1, l1);
        bsplit(v.z, h2, l2); bsplit(v.w, h3, l3);
        __nv_bfloat162 ph0 = {h0, h1}, ph1 = {h2, h3};
        __nv_bfloat162 pl0 = {l0, l1}, pl1 = {l2, l3};
        uint2 uh = {*(uint32_t*)&ph0, *(uint32_t*)&ph1};
        uint2 ul = {*(uint32_t*)&pl0, *(uint32_t*)&pl1};
        ((uint2*)g_wih)[tid] = uh;
        ((uint2*)g_wil)[tid] = ul;
    }
    if (tid < G4H) g_bias[tid] = bi[tid] + bh[tid];
    // clear h-exchange tags (must be re-done every launch for graph replays)
    if (tid < 8 * 2 * 8 * 256) ((ull*)g_hex)[tid] = 0ull;
}

// ---------------------------------------------------------------------------
// Kernel 1: bf16x3 GEMM via mma.sync.m16n8k16  (unchanged, known-good)
// ---------------------------------------------------------------------------
#define LDP 40

__global__ void __launch_bounds__(256) gemm_mma_kernel()
{
    __shared__ __nv_bfloat16 Ah[128][LDP], Al[128][LDP];
    __shared__ __nv_bfloat16 Bh[128][LDP], Bl[128][LDP];

    const int tid = threadIdx.x;
    const int w = tid >> 5, l = tid & 31;
    const int m0 = blockIdx.y * 128, n0 = blockIdx.x * 128;
    const int wm = w & 1;
    const int wn = w >> 1;

    float acc[4][4][4];
#pragma unroll
    for (int mi = 0; mi < 4; mi++)
#pragma unroll
        for (int ni = 0; ni < 4; ni++)
#pragma unroll
            for (int q = 0; q < 4; q++) acc[mi][ni][q] = 0.f;

    for (int kc = 0; kc < KIN; kc += 32) {
#pragma unroll
        for (int tb = 0; tb < 4; tb++) {
            const __nv_bfloat16* src =
                (tb == 0) ? g_xh : (tb == 1) ? g_xl : (tb == 2) ? g_wih : g_wil;
            const int row0 = (tb < 2) ? m0 : n0;
            __nv_bfloat16 (*dst)[LDP] =
                (tb == 0) ? Ah : (tb == 1) ? Al : (tb == 2) ? Bh : Bl;
#pragma unroll
            for (int i = tid; i < 512; i += 256) {
                int r = i >> 2, q = i & 3;
                uint4 v = *(const uint4*)(src + (size_t)(row0 + r) * KIN + kc + q * 8);
                *(uint2*)&dst[r][q * 8]     = make_uint2(v.x, v.y);
                *(uint2*)&dst[r][q * 8 + 4] = make_uint2(v.z, v.w);
            }
        }
        __syncthreads();

#pragma unroll
        for (int p = 0; p < 3; p++) {
            const __nv_bfloat16 (*Ap)[LDP] = (p == 2) ? Al : Ah;
            const __nv_bfloat16 (*Bp)[LDP] = (p == 1) ? Bl : Bh;
#pragma unroll
            for (int ks = 0; ks < 2; ks++) {
                uint32_t af[4][4], bf[4][2];
#pragma unroll
                for (int mi = 0; mi < 4; mi++)
                    ldm_x4(af[mi], smem_u32(
                        &Ap[wm * 64 + mi * 16 + (l & 15)][ks * 16 + (l >> 4) * 8]));
#pragma unroll
                for (int ni = 0; ni < 4; ni++)
                    ldm_x2(bf[ni], smem_u32(
                        &Bp[wn * 32 + ni * 8 + (l & 7)][ks * 16 + ((l >> 3) & 1) * 8]));
#pragma unroll
                for (int mi = 0; mi < 4; mi++)
#pragma unroll
                    for (int ni = 0; ni < 4; ni++)
                        mma16816(acc[mi][ni], af[mi], bf[ni]);
            }
        }
        __syncthreads();
    }

#pragma unroll
    for (int ni = 0; ni < 4; ni++) {
        const int gn = n0 + wn * 32 + ni * 8 + (l & 3) * 2;
        const float b0 = g_bias[gn], b1 = g_bias[gn + 1];
#pragma unroll
        for (int mi = 0; mi < 4; mi++) {
            const int gm = m0 + wm * 64 + mi * 16 + (l >> 2);
            float2 v0 = {acc[mi][ni][0] + b0, acc[mi][ni][1] + b1};
            float2 v1 = {acc[mi][ni][2] + b0, acc[mi][ni][3] + b1};
            *(float2*)&g_preact[(size_t)gm * G4H + gn]       = v0;
            *(float2*)&g_preact[(size_t)(gm + 8) * G4H + gn] = v1;
        }
    }
}

// ---------------------------------------------------------------------------
// Kernel 2: recurrent kernel — tagged polling + TENSOR-CORE hidden GEMM.
// 128 blocks = 16 j-slices x 8 batch-slices.
// A = Wh slice (64 rows = 4 gates x 16 j, K=256) as bf16 hi/lo mma fragments
//     held PERMANENTLY in registers (loaded once via validated ldmatrix path).
// B = h (N=8 batch) converted to bf16 hi/lo during the poll phase.
// Warp w: gate = w&3 (m-tile), khalf = w>>2 (128 k each); bf16x3 = 3 indep
// accumulator chains; k-halves reduced via transposed creds buffer.
// ---------------------------------------------------------------------------
#define HBP 272   // bf16 row pad: 544B rows = 34x16B (16B-aligned, ldm-safe)

__global__ void __launch_bounds__(256, 1) lstm_rec_tc(
    const float* __restrict__ h0, const float* __restrict__ c0,
    const float* __restrict__ Wh, float* __restrict__ out)
{
    __shared__ __nv_bfloat16 wsh[16][HBP], wsl[16][HBP];   // Wh staging
    __shared__ __nv_bfloat16 hbh[8][HBP], hbl[8][HBP];     // h bf16 hi/lo
    __shared__ float creds[4][2][4][33];                   // [gate][kh][reg][lane]

    const int u   = threadIdx.x;
    const int jb  = blockIdx.x & 15;
    const int bb  = blockIdx.x >> 4;
    const int j0  = jb * 16;
    const int b0  = bb * 8;

    const int wid  = u >> 5;
    const int l    = u & 31;
    const int gate = wid & 3;
    const int kh   = wid >> 2;          // k-half (128 k each)

    // poll assignment: thread owns 8 consecutive j of one batch row
    const int pb = u >> 5;              // batch row 0..7
    const int pj = (u & 31) * 8;        // j base 0..248

    // ---- stage Wh -> registers as mma A-fragments (hi/lo), 4 passes ------
    uint32_t ah[8][4], al[8][4];
    for (int pass = 0; pass < 4; pass++) {
        for (int idx = u; idx < 16 * 256; idx += 256) {
            int r = idx >> 8, c = idx & 255;
            float w = Wh[((size_t)pass * HID + j0 + r) * HID + c];
            __nv_bfloat16 hh, ll;
            bsplit(w, hh, ll);
            wsh[r][c] = hh;
            wsl[r][c] = ll;
        }
        __syncthreads();
        if (gate == pass) {
#pragma unroll
            for (int ks = 0; ks < 8; ks++) {
                const int kc = (kh * 8 + ks) * 16;
                ldm_x4(ah[ks], smem_u32(&wsh[l & 15][kc + (l >> 4) * 8]));
                ldm_x4(al[ks], smem_u32(&wsl[l & 15][kc + (l >> 4) * 8]));
            }
        }
        __syncthreads();
    }

    const int tb = u >> 4;   // 0..7  (gates threads, u<128)
    const int tj = u & 15;
    float cst = 0.f, hlast = 0.f;
    if (u < 128) cst = c0[(b0 + tb) * HID + j0 + tj];

    // ---- preload h0 -> bf16 hi/lo in smem --------------------------------
    {
        float4 v0 = *(const float4*)&h0[(size_t)(b0 + pb) * HID + pj];
        float4 v1 = *(const float4*)&h0[(size_t)(b0 + pb) * HID + pj + 4];
        float v[8] = {v0.x, v0.y, v0.z, v0.w, v1.x, v1.y, v1.z, v1.w};
        uint32_t hp[4], lp[4];
#pragma unroll
        for (int i = 0; i < 4; i++) {
            __nv_bfloat16 e0, e1, f0, f1;
            bsplit(v[2 * i], e0, f0); bsplit(v[2 * i + 1], e1, f1);
            __nv_bfloat162 he = {e0, e1}, le = {f0, f1};
            hp[i] = *(uint32_t*)&he; lp[i] = *(uint32_t*)&le;
        }
        *(uint4*)&hbh[pb][pj] = make_uint4(hp[0], hp[1], hp[2], hp[3]);
        *(uint4*)&hbl[pb][pj] = make_uint4(lp[0], lp[1], lp[2], lp[3]);
    }

    // preact for t=0
    float px0 = 0.f, px1 = 0.f, px2 = 0.f, px3 = 0.f;
    if (u < 128) {
        const float* pp = g_preact + ((size_t)(b0 + tb)) * G4H + j0 + tj;
        px0 = pp[0 * HID]; px1 = pp[1 * HID]; px2 = pp[2 * HID]; px3 = pp[3 * HID];
    }
    __syncthreads();

    // gates-side creds addressing (C frag mapping: lane=(r%8)*4+n/2, reg=2*(r/8)+n%2)
    const int glane = (tj & 7) * 4 + (tb >> 1);
    const int greg  = (tb & 1) + 2 * (tj >> 3);

    for (int t = 0; t < SEQ; t++) {
        // prefetch preact t+1
        float nx0 = 0.f, nx1 = 0.f, nx2 = 0.f, nx3 = 0.f;
        if (u < 128) {
            int tn = (t + 1 < SEQ) ? (t + 1) : t;
            const float* pp = g_preact + ((size_t)tn * BATCH + b0 + tb) * G4H + j0 + tj;
            nx0 = pp[0 * HID]; nx1 = pp[1 * HID]; nx2 = pp[2 * HID]; nx3 = pp[3 * HID];
        }

        // ---- tensor-core GEMM: 3 independent bf16x3 accumulator chains ---
        float c1[4] = {0.f, 0.f, 0.f, 0.f};
        float c2[4] = {0.f, 0.f, 0.f, 0.f};
        float c3[4] = {0.f, 0.f, 0.f, 0.f};
#pragma unroll
        for (int ks = 0; ks < 8; ks++) {
            const int kc = (kh * 8 + ks) * 16;
            uint32_t bh2[2], bl2[2];
            ldm_x2(bh2, smem_u32(&hbh[l & 7][kc + ((l >> 3) & 1) * 8]));
            ldm_x2(bl2, smem_u32(&hbl[l & 7][kc + ((l >> 3) & 1) * 8]));
            mma16816(c1, ah[ks], bh2);
            mma16816(c2, ah[ks], bl2);
            mma16816(c3, al[ks], bh2);
        }
#pragma unroll
        for (int q = 0; q < 4; q++)
            creds[gate][kh][q][l] = c1[q] + c2[q] + c3[q];
        __syncthreads();

        // ---- gates + publish (u < 128) -----------------------------------
        if (u < 128) {
            float p[4];
#pragma unroll
            for (int g = 0; g < 4; g++)
                p[g] = creds[g][0][greg][glane] + creds[g][1][greg][glane];
            p[0] += px0; p[1] += px1; p[2] += px2; p[3] += px3;

            float it = sigf(p[0]);
            float ft = sigf(p[1]);
            float ot = sigf(p[2]);
            float gt = tanhf_(p[3]);
            cst = cst * ft + it * gt;
            float ht = ot * tanhf_(cst);
            hlast = ht;

            // publish FIRST (critical path for peers), then local output
            if (t < SEQ - 1) {
                ull pub = ((ull)(uint32_t)(t + 1) << 32)
                        | (ull)__float_as_uint(ht);
                st_rlx_u64(&g_hex[bb][(t + 1) & 1][tb][j0 + tj], pub);
            }
            out[((size_t)t * BATCH + b0 + tb) * HID + j0 + tj] = ht;
        }

        // ---- poll h(t+1), convert to bf16 hi/lo, fill smem ---------------
        if (t < SEQ - 1) {
            const ull* p = &g_hex[bb][(t + 1) & 1][pb][pj];
            const uint32_t tg = (uint32_t)(t + 1);
            ulonglong2 v0, v1, v2, v3;
            while (true) {
                v0 = ld_rlx_v2u64(p + 0);
                v1 = ld_rlx_v2u64(p + 2);
                v2 = ld_rlx_v2u64(p + 4);
                v3 = ld_rlx_v2u64(p + 6);
                bool ok = ((uint32_t)(v0.x >> 32) == tg) &
                          ((uint32_t)(v0.y >> 32) == tg) &
                          ((uint32_t)(v1.x >> 32) == tg) &
                          ((uint32_t)(v1.y >> 32) == tg) &
                          ((uint32_t)(v2.x >> 32) == tg) &
                          ((uint32_t)(v2.y >> 32) == tg) &
                          ((uint32_t)(v3.x >> 32) == tg) &
                          ((uint32_t)(v3.y >> 32) == tg);
                if (ok) break;
            }
            float v[8] = {
                __uint_as_float((uint32_t)v0.x), __uint_as_float((uint32_t)v0.y),
                __uint_as_float((uint32_t)v1.x), __uint_as_float((uint32_t)v1.y),
                __uint_as_float((uint32_t)v2.x), __uint_as_float((uint32_t)v2.y),
                __uint_as_float((uint32_t)v3.x), __uint_as_float((uint32_t)v3.y)};
            uint32_t hp[4], lp[4];
#pragma unroll
            for (int i = 0; i < 4; i++) {
                __nv_bfloat16 e0, e1, f0, f1;
                bsplit(v[2 * i], e0, f0); bsplit(v[2 * i + 1], e1, f1);
                __nv_bfloat162 he = {e0, e1}, le = {f0, f1};
                hp[i] = *(uint32_t*)&he; lp[i] = *(uint32_t*)&le;
            }
            *(uint4*)&hbh[pb][pj] = make_uint4(hp[0], hp[1], hp[2], hp[3]);
            *(uint4*)&hbl[pb][pj] = make_uint4(lp[0], lp[1], lp[2], lp[3]);
        }
        __syncthreads();

        px0 = nx0; px1 = nx1; px2 = nx2; px3 = nx3;
    }

    if (u < 128) {
        const size_t base = (size_t)SEQ * BATCH * HID;
        const int idx = (b0 + tb) * HID + j0 + tj;
        out[base + idx]               = hlast;
        out[base + BATCH * HID + idx] = cst;
    }
}

// ---------------------------------------------------------------------------
extern "C" void kernel_launch(void* const* d_in, const int* in_sizes, int n_in,
                              void* d_out, int out_size)
{
    const float* x  = (const float*)d_in[0];
    const float* h0 = (const float*)d_in[1];
    const float* c0 = (const float*)d_in[2];
    const float* Wi = (const float*)d_in[3];
    const float* bi = (const float*)d_in[4];
    const float* Wh = (const float*)d_in[5];
    const float* bh = (const float*)d_in[6];
    float* out = (float*)d_out;

    convert_x_kernel<<<8192, 256>>>(x);
    convert_w_kernel<<<256, 256>>>(Wi, bi, bh);

    dim3 gg(G4H / 128, MTOT / 128);
    gemm_mma_kernel<<<gg, 256>>>();

    lstm_rec_tc<<<128, 256>>>(h0, c0, Wh, out);
}

// round 16
// speedup vs baseline: 2.3921x; 1.0215x over previous
#include <cuda_runtime.h>
#include <cuda_bf16.h>
#include <cstdint>

typedef unsigned long long ull;

#define SEQ   2048
#define BATCH 64
#define KIN   256
#define HID   256
#define G4H   1024   // 4*HID
#define MTOT  (SEQ * BATCH)   // 131072

// ---------------- scratch (device globals; no allocation allowed) ----------
__device__ float g_preact[(size_t)SEQ * BATCH * G4H];          // 512 MB
__device__ __nv_bfloat16 g_xh[(size_t)MTOT * KIN];             // 64 MB
__device__ __nv_bfloat16 g_xl[(size_t)MTOT * KIN];             // 64 MB
__device__ __nv_bfloat16 g_wih[(size_t)G4H * KIN];
__device__ __nv_bfloat16 g_wil[(size_t)G4H * KIN];
__device__ float g_bias[G4H];
// tagged h exchange: [batch-slice][parity][b][j] = {u32 tag, f32 value} packed
__device__ __align__(16) ull g_hex[8][2][8][256];              // 256 KB

// ---------------- small helpers -------------------------------------------
__device__ __forceinline__ uint32_t smem_u32(const void* p) {
    uint32_t a;
    asm("{ .reg .u64 t; cvta.to.shared.u64 t, %1; cvt.u32.u64 %0, t; }"
        : "=r"(a) : "l"(p));
    return a;
}
__device__ __forceinline__ float sigf(float x) {
    return __fdividef(1.f, 1.f + __expf(-x));
}
__device__ __forceinline__ float tanhf_(float x) { return 2.f * sigf(2.f * x) - 1.f; }

__device__ __forceinline__ void ldm_x4(uint32_t* r, uint32_t addr) {
    asm volatile("ldmatrix.sync.aligned.m8n8.x4.shared.b16 {%0,%1,%2,%3}, [%4];"
                 : "=r"(r[0]), "=r"(r[1]), "=r"(r[2]), "=r"(r[3]) : "r"(addr));
}
__device__ __forceinline__ void ldm_x2(uint32_t* r, uint32_t addr) {
    asm volatile("ldmatrix.sync.aligned.m8n8.x2.shared.b16 {%0,%1}, [%2];"
                 : "=r"(r[0]), "=r"(r[1]) : "r"(addr));
}
__device__ __forceinline__ void mma16816(float* d, const uint32_t* a,
                                         const uint32_t* b) {
    asm volatile(
        "mma.sync.aligned.m16n8k16.row.col.f32.bf16.bf16.f32 "
        "{%0,%1,%2,%3}, {%4,%5,%6,%7}, {%8,%9}, {%0,%1,%2,%3};"
        : "+f"(d[0]), "+f"(d[1]), "+f"(d[2]), "+f"(d[3])
        : "r"(a[0]), "r"(a[1]), "r"(a[2]), "r"(a[3]), "r"(b[0]), "r"(b[1]));
}

// cp.async primitives (Ampere+ baseline, sm_103-safe)
__device__ __forceinline__ void cpa16(uint32_t dst, const void* src) {
    asm volatile("cp.async.cg.shared.global [%0], [%1], 16;"
                 :: "r"(dst), "l"(__cvta_generic_to_global(src)) : "memory");
}
__device__ __forceinline__ void cpa_commit() {
    asm volatile("cp.async.commit_group;" ::: "memory");
}
template <int N>
__device__ __forceinline__ void cpa_wait() {
    asm volatile("cp.async.wait_group %0;" :: "n"(N) : "memory");
}

// tagged-word publish / poll primitives (plain L2-coherent relaxed ops)
__device__ __forceinline__ void st_rlx_u64(ull* p, ull v) {
    asm volatile("st.relaxed.gpu.global.u64 [%0], %1;" :: "l"(p), "l"(v)
                 : "memory");
}
__device__ __forceinline__ ulonglong2 ld_rlx_v2u64(const ull* p) {
    ulonglong2 v;
    asm volatile("ld.relaxed.gpu.global.v2.u64 {%0,%1}, [%2];"
                 : "=l"(v.x), "=l"(v.y) : "l"(p) : "memory");
    return v;
}

// bf16 hi/lo split of a float
__device__ __forceinline__ void bsplit(float v, __nv_bfloat16& h, __nv_bfloat16& l) {
    h = __float2bfloat16(v);
    l = __float2bfloat16(v - __bfloat162float(h));
}

// ---------------------------------------------------------------------------
// Kernel 0a: convert x -> bf16 hi/lo planes
// ---------------------------------------------------------------------------
__global__ void __launch_bounds__(256) convert_x_kernel(const float* __restrict__ x)
{
    const size_t n4 = (size_t)MTOT * KIN / 4;
    for (size_t i = (size_t)blockIdx.x * blockDim.x + threadIdx.x; i < n4;
         i += (size_t)gridDim.x * blockDim.x) {
        float4 v = ((const float4*)x)[i];
        __nv_bfloat16 h0, h1, h2, h3, l0, l1, l2, l3;
        bsplit(v.x, h0, l0); bsplit(v.y, h1, l1);
        bsplit(v.z, h2, l2); bsplit(v.w, h3, l3);
        __nv_bfloat162 ph0 = {h0, h1}, ph1 = {h2, h3};
        __nv_bfloat162 pl0 = {l0, l1}, pl1 = {l2, l3};
        uint2 uh = {*(uint32_t*)&ph0, *(uint32_t*)&ph1};
        uint2 ul = {*(uint32_t*)&pl0, *(uint32_t*)&pl1};
        ((uint2*)g_xh)[i] = uh;
        ((uint2*)g_xl)[i] = ul;
    }
}

// ---------------------------------------------------------------------------
// Kernel 0b: convert Wi -> bf16 hi/lo, combine bias, clear exchange tags
// ---------------------------------------------------------------------------
__global__ void __launch_bounds__(256) convert_w_kernel(
    const float* __restrict__ Wi, const float* __restrict__ bi,
    const float* __restrict__ bh)
{
    const size_t tid = (size_t)blockIdx.x * blockDim.x + threadIdx.x;
    const size_t n4 = (size_t)G4H * KIN / 4;   // 65536
    if (tid < n4) {
        float4 v = ((const float4*)Wi)[tid];
        __nv_bfloat16 h0, h1, h2, h3, l0, l1, l2, l3;
        bsplit(v.x, h0, l0); bsplit(v.y, h1, l1);
        bsplit(v.z, h2, l2); bsplit(v.w, h3, l3);
        __nv_bfloat162 ph0 = {h0, h1}, ph1 = {h2, h3};
        __nv_bfloat162 pl0 = {l0, l1}, pl1 = {l2, l3};
        uint2 uh = {*(uint32_t*)&ph0, *(uint32_t*)&ph1};
        uint2 ul = {*(uint32_t*)&pl0, *(uint32_t*)&pl1};
        ((uint2*)g_wih)[tid] = uh;
        ((uint2*)g_wil)[tid] = ul;
    }
    if (tid < G4H) g_bias[tid] = bi[tid] + bh[tid];
    // clear h-exchange tags (must be re-done every launch for graph replays)
    if (tid < 8 * 2 * 8 * 256) ((ull*)g_hex)[tid] = 0ull;
}

// ---------------------------------------------------------------------------
// Kernel 1: bf16x3 GEMM via mma.sync — cp.async 2-STAGE PIPELINE.
//   Same tiles/fragments/epilogue as the proven kernel; only the smem fill
//   path changed: loads for chunk c+1 stream via LDGSTS while chunk c's mma
//   runs. Dynamic smem: 2 stages x 4 tiles x 128 x LDP bf16 = 80 KB.
// ---------------------------------------------------------------------------
#define LDP 40
#define TILE_ELEMS (128 * LDP)
#define GSM (2 * 4 * TILE_ELEMS * 2)   // bytes = 81920

__global__ void __launch_bounds__(256) gemm_mma_async()
{
    extern __shared__ __nv_bfloat16 buf[];   // [2][4][128][LDP]

    const int tid = threadIdx.x;
    const int w = tid >> 5, l = tid & 31;
    const int m0 = blockIdx.y * 128, n0 = blockIdx.x * 128;
    const int wm = w & 1;
    const int wn = w >> 1;

    // per-thread load coordinates (2 transfers per tile)
    const int i0 = tid * 2, i1 = tid * 2 + 1;
    const int r0 = i0 >> 2, q0 = i0 & 3;
    const int r1 = i1 >> 2, q1 = i1 & 3;

    const __nv_bfloat16* srcs[4] = {g_xh, g_xl, g_wih, g_wil};

    auto issue_chunk = [&](int kc, int st) {
#pragma unroll
        for (int t = 0; t < 4; t++) {
            const __nv_bfloat16* src = srcs[t];
            const int row0 = (t < 2) ? m0 : n0;
            __nv_bfloat16* dst = buf + (st * 4 + t) * TILE_ELEMS;
            cpa16(smem_u32(dst + r0 * LDP + q0 * 8),
                  src + (size_t)(row0 + r0) * KIN + kc + q0 * 8);
            cpa16(smem_u32(dst + r1 * LDP + q1 * 8),
                  src + (size_t)(row0 + r1) * KIN + kc + q1 * 8);
        }
        cpa_commit();
    };

    float acc[4][4][4];
#pragma unroll
    for (int mi = 0; mi < 4; mi++)
#pragma unroll
        for (int ni = 0; ni < 4; ni++)
#pragma unroll
            for (int q = 0; q < 4; q++) acc[mi][ni][q] = 0.f;

    issue_chunk(0, 0);

    for (int c = 0; c < 8; c++) {
        const int st = c & 1;
        if (c + 1 < 8) {
            issue_chunk((c + 1) * 32, st ^ 1);
            cpa_wait<1>();     // chunk c complete; c+1 may remain in flight
        } else {
            cpa_wait<0>();
        }
        __syncthreads();

#pragma unroll
        for (int p = 0; p < 3; p++) {
            const __nv_bfloat16* Ap = buf + (st * 4 + (p == 2 ? 1 : 0)) * TILE_ELEMS;
            const __nv_bfloat16* Bp = buf + (st * 4 + 2 + (p == 1 ? 1 : 0)) * TILE_ELEMS;
#pragma unroll
            for (int ks = 0; ks < 2; ks++) {
                uint32_t af[4][4], bf[4][2];
#pragma unroll
                for (int mi = 0; mi < 4; mi++)
                    ldm_x4(af[mi], smem_u32(
                        Ap + (wm * 64 + mi * 16 + (l & 15)) * LDP
                           + ks * 16 + (l >> 4) * 8));
#pragma unroll
                for (int ni = 0; ni < 4; ni++)
                    ldm_x2(bf[ni], smem_u32(
                        Bp + (wn * 32 + ni * 8 + (l & 7)) * LDP
                           + ks * 16 + ((l >> 3) & 1) * 8));
#pragma unroll
                for (int mi = 0; mi < 4; mi++)
#pragma unroll
                    for (int ni = 0; ni < 4; ni++)
                        mma16816(acc[mi][ni], af[mi], bf[ni]);
            }
        }
        __syncthreads();   // mma reads done before stage st is refilled (c+2)
    }

#pragma unroll
    for (int ni = 0; ni < 4; ni++) {
        const int gn = n0 + wn * 32 + ni * 8 + (l & 3) * 2;
        const float b0 = g_bias[gn], b1 = g_bias[gn + 1];
#pragma unroll
        for (int mi = 0; mi < 4; mi++) {
            const int gm = m0 + wm * 64 + mi * 16 + (l >> 2);
            float2 v0 = {acc[mi][ni][0] + b0, acc[mi][ni][1] + b1};
            float2 v1 = {acc[mi][ni][2] + b0, acc[mi][ni][3] + b1};
            *(float2*)&g_preact[(size_t)gm * G4H + gn]       = v0;
            *(float2*)&g_preact[(size_t)(gm + 8) * G4H + gn] = v1;
        }
    }
}

// ---------------------------------------------------------------------------
// Kernel 2: recurrent kernel — tagged polling + tensor-core hidden GEMM.
// (UNCHANGED from round 15 — proven at 2.65 ms.)
// ---------------------------------------------------------------------------
#define HBP 272   // bf16 row pad: 544B rows = 34x16B (16B-aligned, ldm-safe)

__global__ void __launch_bounds__(256, 1) lstm_rec_tc(
    const float* __restrict__ h0, const float* __restrict__ c0,
    const float* __restrict__ Wh, float* __restrict__ out)
{
    __shared__ __nv_bfloat16 wsh[16][HBP], wsl[16][HBP];   // Wh staging
    __shared__ __nv_bfloat16 hbh[8][HBP], hbl[8][HBP];     // h bf16 hi/lo
    __shared__ float creds[4][2][4][33];                   // [gate][kh][reg][lane]

    const int u   = threadIdx.x;
    const int jb  = blockIdx.x & 15;
    const int bb  = blockIdx.x >> 4;
    const int j0  = jb * 16;
    const int b0  = bb * 8;

    const int wid  = u >> 5;
    const int l    = u & 31;
    const int gate = wid & 3;
    const int kh   = wid >> 2;          // k-half (128 k each)

    // poll assignment: thread owns 8 consecutive j of one batch row
    const int pb = u >> 5;              // batch row 0..7
    const int pj = (u & 31) * 8;        // j base 0..248

    // ---- stage Wh -> registers as mma A-fragments (hi/lo), 4 passes ------
    uint32_t ah[8][4], al[8][4];
    for (int pass = 0; pass < 4; pass++) {
        for (int idx = u; idx < 16 * 256; idx += 256) {
            int r = idx >> 8, c = idx & 255;
            float w = Wh[((size_t)pass * HID + j0 + r) * HID + c];
            __nv_bfloat16 hh, ll;
            bsplit(w, hh, ll);
            wsh[r][c] = hh;
            wsl[r][c] = ll;
        }
        __syncthreads();
        if (gate == pass) {
#pragma unroll
            for (int ks = 0; ks < 8; ks++) {
                const int kc = (kh * 8 + ks) * 16;
                ldm_x4(ah[ks], smem_u32(&wsh[l & 15][kc + (l >> 4) * 8]));
                ldm_x4(al[ks], smem_u32(&wsl[l & 15][kc + (l >> 4) * 8]));
            }
        }
        __syncthreads();
    }

    const int tb = u >> 4;   // 0..7  (gates threads, u<128)
    const int tj = u & 15;
    float cst = 0.f, hlast = 0.f;
    if (u < 128) cst = c0[(b0 + tb) * HID + j0 + tj];

    // ---- preload h0 -> bf16 hi/lo in smem --------------------------------
    {
        float4 v0 = *(const float4*)&h0[(size_t)(b0 + pb) * HID + pj];
        float4 v1 = *(const float4*)&h0[(size_t)(b0 + pb) * HID + pj + 4];
        float v[8] = {v0.x, v0.y, v0.z, v0.w, v1.x, v1.y, v1.z, v1.w};
        uint32_t hp[4], lp[4];
#pragma unroll
        for (int i = 0; i < 4; i++) {
            __nv_bfloat16 e0, e1, f0, f1;
            bsplit(v[2 * i], e0, f0); bsplit(v[2 * i + 1], e1, f1);
            __nv_bfloat162 he = {e0, e1}, le = {f0, f1};
            hp[i] = *(uint32_t*)&he; lp[i] = *(uint32_t*)&le;
        }
        *(uint4*)&hbh[pb][pj] = make_uint4(hp[0], hp[1], hp[2], hp[3]);
        *(uint4*)&hbl[pb][pj] = make_uint4(lp[0], lp[1], lp[2], lp[3]);
    }

    // preact for t=0
    float px0 = 0.f, px1 = 0.f, px2 = 0.f, px3 = 0.f;
    if (u < 128) {
        const float* pp = g_preact + ((size_t)(b0 + tb)) * G4H + j0 + tj;
        px0 = pp[0 * HID]; px1 = pp[1 * HID]; px2 = pp[2 * HID]; px3 = pp[3 * HID];
    }
    __syncthreads();

    // gates-side creds addressing (C frag: lane=(r%8)*4+n/2, reg=2*(r/8)+n%2)
    const int glane = (tj & 7) * 4 + (tb >> 1);
    const int greg  = (tb & 1) + 2 * (tj >> 3);

    for (int t = 0; t < SEQ; t++) {
        // prefetch preact t+1
        float nx0 = 0.f, nx1 = 0.f, nx2 = 0.f, nx3 = 0.f;
        if (u < 128) {
            int tn = (t + 1 < SEQ) ? (t + 1) : t;
            const float* pp = g_preact + ((size_t)tn * BATCH + b0 + tb) * G4H + j0 + tj;
            nx0 = pp[0 * HID]; nx1 = pp[1 * HID]; nx2 = pp[2 * HID]; nx3 = pp[3 * HID];
        }

        // ---- tensor-core GEMM: 3 independent bf16x3 accumulator chains ---
        float c1[4] = {0.f, 0.f, 0.f, 0.f};
        float c2[4] = {0.f, 0.f, 0.f, 0.f};
        float c3[4] = {0.f, 0.f, 0.f, 0.f};
#pragma unroll
        for (int ks = 0; ks < 8; ks++) {
            const int kc = (kh * 8 + ks) * 16;
            uint32_t bh2[2], bl2[2];
            ldm_x2(bh2, smem_u32(&hbh[l & 7][kc + ((l >> 3) & 1) * 8]));
            ldm_x2(bl2, smem_u32(&hbl[l & 7][kc + ((l >> 3) & 1) * 8]));
            mma16816(c1, ah[ks], bh2);
            mma16816(c2, ah[ks], bl2);
            mma16816(c3, al[ks], bh2);
        }
#pragma unroll
        for (int q = 0; q < 4; q++)
            creds[gate][kh][q][l] = c1[q] + c2[q] + c3[q];
        __syncthreads();

        // ---- gates + publish (u < 128) -----------------------------------
        if (u < 128) {
            float p[4];
#pragma unroll
            for (int g = 0; g < 4; g++)
                p[g] = creds[g][0][greg][glane] + creds[g][1][greg][glane];
            p[0] += px0; p[1] += px1; p[2] += px2; p[3] += px3;

            float it = sigf(p[0]);
            float ft = sigf(p[1]);
            float ot = sigf(p[2]);
            float gt = tanhf_(p[3]);
            cst = cst * ft + it * gt;
            float ht = ot * tanhf_(cst);
            hlast = ht;

            // publish FIRST (critical path for peers), then local output
            if (t < SEQ - 1) {
                ull pub = ((ull)(uint32_t)(t + 1) << 32)
                        | (ull)__float_as_uint(ht);
                st_rlx_u64(&g_hex[bb][(t + 1) & 1][tb][j0 + tj], pub);
            }
            out[((size_t)t * BATCH + b0 + tb) * HID + j0 + tj] = ht;
        }

        // ---- poll h(t+1), convert to bf16 hi/lo, fill smem ---------------
        if (t < SEQ - 1) {
            const ull* p = &g_hex[bb][(t + 1) & 1][pb][pj];
            const uint32_t tg = (uint32_t)(t + 1);
            ulonglong2 v0, v1, v2, v3;
            while (true) {
                v0 = ld_rlx_v2u64(p + 0);
                v1 = ld_rlx_v2u64(p + 2);
                v2 = ld_rlx_v2u64(p + 4);
                v3 = ld_rlx_v2u64(p + 6);
                bool ok = ((uint32_t)(v0.x >> 32) == tg) &
                          ((uint32_t)(v0.y >> 32) == tg) &
                          ((uint32_t)(v1.x >> 32) == tg) &
                          ((uint32_t)(v1.y >> 32) == tg) &
                          ((uint32_t)(v2.x >> 32) == tg) &
                          ((uint32_t)(v2.y >> 32) == tg) &
                          ((uint32_t)(v3.x >> 32) == tg) &
                          ((uint32_t)(v3.y >> 32) == tg);
                if (ok) break;
            }
            float v[8] = {
                __uint_as_float((uint32_t)v0.x), __uint_as_float((uint32_t)v0.y),
                __uint_as_float((uint32_t)v1.x), __uint_as_float((uint32_t)v1.y),
                __uint_as_float((uint32_t)v2.x), __uint_as_float((uint32_t)v2.y),
                __uint_as_float((uint32_t)v3.x), __uint_as_float((uint32_t)v3.y)};
            uint32_t hp[4], lp[4];
#pragma unroll
            for (int i = 0; i < 4; i++) {
                __nv_bfloat16 e0, e1, f0, f1;
                bsplit(v[2 * i], e0, f0); bsplit(v[2 * i + 1], e1, f1);
                __nv_bfloat162 he = {e0, e1}, le = {f0, f1};
                hp[i] = *(uint32_t*)&he; lp[i] = *(uint32_t*)&le;
            }
            *(uint4*)&hbh[pb][pj] = make_uint4(hp[0], hp[1], hp[2], hp[3]);
            *(uint4*)&hbl[pb][pj] = make_uint4(lp[0], lp[1], lp[2], lp[3]);
        }
        __syncthreads();

        px0 = nx0; px1 = nx1; px2 = nx2; px3 = nx3;
    }

    if (u < 128) {
        const size_t base = (size_t)SEQ * BATCH * HID;
        const int idx = (b0 + tb) * HID + j0 + tj;
        out[base + idx]               = hlast;
        out[base + BATCH * HID + idx] = cst;
    }
}

// ---------------------------------------------------------------------------
extern "C" void kernel_launch(void* const* d_in, const int* in_sizes, int n_in,
                              void* d_out, int out_size)
{
    const float* x  = (const float*)d_in[0];
    const float* h0 = (const float*)d_in[1];
    const float* c0 = (const float*)d_in[2];
    const float* Wi = (const float*)d_in[3];
    const float* bi = (const float*)d_in[4];
    const float* Wh = (const float*)d_in[5];
    const float* bh = (const float*)d_in[6];
    float* out = (float*)d_out;

    cudaFuncSetAttribute(gemm_mma_async,
                         cudaFuncAttributeMaxDynamicSharedMemorySize, GSM);

    convert_x_kernel<<<8192, 256>>>(x);
    convert_w_kernel<<<256, 256>>>(Wi, bi, bh);

    dim3 gg(G4H / 128, MTOT / 128);
    gemm_mma_async<<<gg, 256, GSM>>>();

    lstm_rec_tc<<<128, 256>>>(h0, c0, Wh, out);
}